// round 13
// baseline (speedup 1.0000x reference)
#include <cuda_runtime.h>
#include <cuda_bf16.h>
#include <cstdint>
#include <cstddef>

#define B_ 8
#define N_ 8192
#define D_ 256

typedef unsigned long long ull;
typedef unsigned int u32;

#if !defined(__CUDA_ARCH__) || defined(__CUDA_ARCH_FEAT_SM103_ALL) || defined(__CUDA_ARCH_FEAT_SM100_ALL) || defined(__CUDA_ARCH_FEAT_SM101_ALL)
#define TCOK 1
#else
#define TCOK 0
#endif

// ---------------- device scratch ----------------
__device__ __nv_bfloat16 g_MTH[B_ * D_ * D_];   // (Wq^T aw)^T hi [b][e][i]
__device__ __nv_bfloat16 g_MTL[B_ * D_ * D_];
__device__ float g_S[B_ * D_ * D_];
__device__ float g_T1[B_ * D_ * D_];
__device__ float g_A[B_ * D_ * D_];
__device__ float g_rk[B_ * D_];
__device__ float g_rv[B_ * D_];
__device__ float g_u[B_ * D_];
__device__ float g_w[B_ * D_];
__device__ float g_t[B_ * D_];
__device__ float g_cm[B_];
__device__ int   g_kind;
__device__ float g_m[B_ * N_];

// ---------------- scalar helpers ----------------
__device__ __forceinline__ ull pack2(float lo, float hi) {
    ull r; asm("mov.b64 %0, {%1,%2};" : "=l"(r) : "f"(lo), "f"(hi)); return r;
}
__device__ __forceinline__ void unpack2(ull v, float& lo, float& hi) {
    asm("mov.b64 {%0,%1}, %2;" : "=f"(lo), "=f"(hi) : "l"(v));
}
__device__ __forceinline__ ull ffma2(ull a, ull b, ull c) {
    ull d; asm("fma.rn.f32x2 %0, %1, %2, %3;" : "=l"(d) : "l"(a), "l"(b), "l"(c)); return d;
}
__device__ __forceinline__ u32 prmt7632(u32 a, u32 b) {
    u32 d; asm("prmt.b32 %0, %1, %2, 0x7632;" : "=r"(d) : "r"(a), "r"(b)); return d;
}
// f32 pair -> bf16x2 hi (truncated) + bf16x2 lo (residual, truncated). err ~2^-16.
__device__ __forceinline__ void cvt2(float x0, float x1, u32& h2, u32& l2) {
    u32 u0 = __float_as_uint(x0), u1 = __float_as_uint(x1);
    h2 = prmt7632(u0, u1);
    float l0 = x0 - __uint_as_float(u0 & 0xFFFF0000u);
    float l1 = x1 - __uint_as_float(u1 & 0xFFFF0000u);
    l2 = prmt7632(__float_as_uint(l0), __float_as_uint(l1));
}

// ---------------- tcgen05 / async helpers (guarded) ----------------
#if TCOK
__device__ __forceinline__ u32 smem_u32(const void* p) {
    u32 a; asm("{ .reg .u64 t; cvta.to.shared.u64 t, %1; cvt.u32.u64 %0, t; }" : "=r"(a) : "l"(p));
    return a;
}
__device__ __forceinline__ int elect1() {
    u32 p;
    asm volatile("{\n\t.reg .pred p;\n\telect.sync _|p, 0xFFFFFFFF;\n\tselp.b32 %0, 1, 0, p;\n\t}" : "=r"(p));
    return (int)p;
}
__device__ __forceinline__ void cp16(u32 dst, const void* src) {
    asm volatile("cp.async.cg.shared.global [%0], [%1], 16;" :: "r"(dst), "l"(src) : "memory");
}
__device__ __forceinline__ void cp_commit() {
    asm volatile("cp.async.commit_group;" ::: "memory");
}
template <int N>
__device__ __forceinline__ void cp_wait() {
    asm volatile("cp.async.wait_group %0;" :: "n"(N) : "memory");
}
__device__ __forceinline__ void mbar_init(u32 mbar, u32 cnt) {
    asm volatile("mbarrier.init.shared.b64 [%0], %1;" :: "r"(mbar), "r"(cnt) : "memory");
}
__device__ __forceinline__ void mbar_inval(u32 mbar) {
    asm volatile("mbarrier.inval.shared.b64 [%0];" :: "r"(mbar) : "memory");
}
__device__ __forceinline__ void mbar_wait(u32 mbar, u32 parity) {
    asm volatile(
        "{\n\t.reg .pred P;\n\t"
        "WL_%=:\n\t"
        "mbarrier.try_wait.parity.acquire.cta.shared::cta.b64 P, [%0], %1, 0x989680;\n\t"
        "@P bra WD_%=;\n\t"
        "bra.uni WL_%=;\n\t"
        "WD_%=:\n\t}"
        :: "r"(mbar), "r"(parity) : "memory");
}
__device__ __forceinline__ void tmem_alloc(u32 smem_dst, u32 ncols) {
    asm volatile("tcgen05.alloc.cta_group::1.sync.aligned.shared::cta.b32 [%0], %1;"
                 :: "r"(smem_dst), "r"(ncols) : "memory");
}
__device__ __forceinline__ void tmem_relinquish() {
    asm volatile("tcgen05.relinquish_alloc_permit.cta_group::1.sync.aligned;");
}
__device__ __forceinline__ void tmem_dealloc(u32 tmem, u32 ncols) {
    asm volatile("tcgen05.dealloc.cta_group::1.sync.aligned.b32 %0, %1;" :: "r"(tmem), "r"(ncols));
}
__device__ __forceinline__ void mma_f16_ss(u32 d_tmem, ull a_desc, ull b_desc, u32 idesc, int accum) {
    u32 z = 0;
    asm volatile(
        "{\n\t.reg .pred p;\n\tsetp.ne.u32 p, %5, 0;\n\t"
        "tcgen05.mma.cta_group::1.kind::f16 [%0], %1, %2, %3, {%4, %4, %4, %4}, p;\n\t}"
        :: "r"(d_tmem), "l"(a_desc), "l"(b_desc), "r"(idesc), "r"(z), "r"((u32)accum) : "memory");
}
__device__ __forceinline__ void mma_commit(u32 mbar) {
    asm volatile("tcgen05.commit.cta_group::1.mbarrier::arrive::one.shared::cluster.b64 [%0];"
                 :: "r"(mbar) : "memory");
}
__device__ __forceinline__ void fence_async_proxy() {
    asm volatile("fence.proxy.async.shared::cta;" ::: "memory");
}
__device__ __forceinline__ void tc_fence_after() {
    asm volatile("tcgen05.fence::after_thread_sync;" ::: "memory");
}
__device__ __forceinline__ void tmem_wait_ld() {
    asm volatile("tcgen05.wait::ld.sync.aligned;" ::: "memory");
}

#define LDTM32(r, addr)                                                      \
    asm volatile("tcgen05.ld.sync.aligned.32x32b.x32.b32 "                   \
        "{%0, %1, %2, %3, %4, %5, %6, %7, %8, %9, %10, %11, %12, %13, %14, %15, " \
        " %16, %17, %18, %19, %20, %21, %22, %23, %24, %25, %26, %27, %28, %29, %30, %31}, [%32];" \
        : "=r"((r)[0]), "=r"((r)[1]), "=r"((r)[2]), "=r"((r)[3]),            \
          "=r"((r)[4]), "=r"((r)[5]), "=r"((r)[6]), "=r"((r)[7]),            \
          "=r"((r)[8]), "=r"((r)[9]), "=r"((r)[10]), "=r"((r)[11]),          \
          "=r"((r)[12]), "=r"((r)[13]), "=r"((r)[14]), "=r"((r)[15]),        \
          "=r"((r)[16]), "=r"((r)[17]), "=r"((r)[18]), "=r"((r)[19]),        \
          "=r"((r)[20]), "=r"((r)[21]), "=r"((r)[22]), "=r"((r)[23]),        \
          "=r"((r)[24]), "=r"((r)[25]), "=r"((r)[26]), "=r"((r)[27]),        \
          "=r"((r)[28]), "=r"((r)[29]), "=r"((r)[30]), "=r"((r)[31])         \
        : "r"(addr))

__device__ __forceinline__ u32 sw64(u32 off)  { return off ^ ((off >> 3) & 0x30); }

#define DESC_BASE64 ((4ull << 61) | (1ull << 46) | (32ull << 32) | (1ull << 16))
__device__ __forceinline__ ull mk_desc64(u32 addr) { return DESC_BASE64 | ((ull)(addr >> 4) & 0x3FFF); }

#define MMA_IDESC 0x8400490u   // F32 accum, BF16xBF16, M=128, N=256
#endif  // TCOK

// ---- k6 layout (2 n-tiles, double-buffered ops) ----
#define SM_TPTR 0
#define MB0 8
#define MB1 16
#define SM_OPS 1024
#define OPSET 65536            // A0H 8K|A0L 8K|A1H 8K|A1L 8K|BH 16K|BL 16K
#define K6_TOTAL (1024 + 2 * OPSET)    // 132096

// ---- k1 layout: mask + fp32 staging (single) + ops (double) ----
#define SM_MASK 1024                   // 32 floats
#define SM_STGK 1152                   // 32 x 260 f32 = 33280
#define SM_STGV (1152 + 33280)         // 34432
#define K1_OPS  68608                  // 1024-aligned
#define K1_TOTAL (K1_OPS + 2 * OPSET)  // 199680

// ---------------- mask detect + canonicalize (+cm) ----------------
__global__ void k_detect(const unsigned char* __restrict__ raw) {
    int idx = blockIdx.x * blockDim.x + threadIdx.x;   // < 16384
    if (raw[idx * 4 + 1] != 0) atomicOr(&g_kind, 1);
}

__global__ void k_maskconv(const void* __restrict__ rawv) {
    int n = blockIdx.x * blockDim.x + threadIdx.x;
    bool padded;
    if (g_kind) padded = ((const unsigned char*)rawv)[n] != 0;
    else        padded = ((const unsigned int*)rawv)[n] != 0u;
    float m = padded ? 0.f : 1.f;
    g_m[n] = m;
    float s = m;
#pragma unroll
    for (int o = 16; o > 0; o >>= 1) s += __shfl_xor_sync(0xffffffffu, s, o);
    __shared__ float red[8];
    int wid = threadIdx.x >> 5, lane = threadIdx.x & 31;
    if (lane == 0) red[wid] = s;
    __syncthreads();
    if (threadIdx.x == 0) {
        float t = 0.f;
        for (int i = 0; i < 8; i++) t += red[i];
        atomicAdd(&g_cm[n >> 13], t);
    }
}

__global__ void k_zero() {
    int i = blockIdx.x * blockDim.x + threadIdx.x;
    if (i < B_ * D_ * D_) g_S[i] = 0.f;
    if (i < B_ * D_) { g_rk[i] = 0.f; g_rv[i] = 0.f; }
    if (i < B_) g_cm[i] = 0.f;
    if (i == 0) g_kind = 0;
}

// ---------------- k1: S[b] = K_m^T V, full-d CTA, cp.async pipelined ---------
// grid (16 chunks, B), 512 threads, single wave. 16 windows of n=32, K=32 SW64.
__global__ void __launch_bounds__(512, 1)
k1_mma(const float* __restrict__ key, const float* __restrict__ value) {
#if TCOK
    extern __shared__ char smem[];
    const u32 sb = smem_u32(smem);
    const int tid = threadIdx.x, wid = tid >> 5, lid = tid & 31;
    const int b = blockIdx.y, chunk = blockIdx.x;
    const int n_start = chunk * 512;

    if (wid == 0) { tmem_alloc(sb + SM_TPTR, 512); tmem_relinquish(); }
    if (tid == 0) { mbar_init(sb + MB0, 1); mbar_init(sb + MB1, 1); }
    __syncthreads();
    u32 tbase;
    asm volatile("ld.shared.b32 %0, [%1];" : "=r"(tbase) : "r"(sb + SM_TPTR));

    const float* smask = (const float*)(smem + SM_MASK);
    const float* stgK  = (const float*)(smem + SM_STGK);
    const float* stgV  = (const float*)(smem + SM_STGV);

    auto stage_issue = [&](int c) {
        const int nw = n_start + c * 32;
        if (tid < 8) cp16(sb + SM_MASK + tid * 16, g_m + (size_t)b * N_ + nw + tid * 4);
#pragma unroll
        for (int k = 0; k < 4; k++) {
            int i = tid + 512 * k;
            int r = i >> 6, cc = i & 63;
            cp16(sb + SM_STGK + r * 1040 + cc * 16,
                 key + ((size_t)b * N_ + nw + r) * D_ + cc * 4);
            cp16(sb + SM_STGV + r * 1040 + cc * 16,
                 value + ((size_t)b * N_ + nw + r) * D_ + cc * 4);
        }
    };

    float skacc = 0.f, svacc = 0.f;

    stage_issue(0);
    cp_commit();

    for (int c = 0; c < 16; c++) {
        const int s = c & 1;
        const u32 ops = sb + K1_OPS + s * OPSET;
        cp_wait<0>();
        __syncthreads();                    // staging(c) visible to all
        if (c >= 2) mbar_wait(sb + (s ? MB1 : MB0), ((c >> 1) - 1) & 1);

        // ---- A: masked key, 256 d-rows x 32 n -> two M=128 tiles ----
#pragma unroll
        for (int k = 0; k < 2; k++) {
            int i = tid + 512 * k;
            int r = i & 255, g = i >> 8;    // r: d, g: 8-n group 0..3
            float f[8], m[8];
#pragma unroll
            for (int j = 0; j < 8; j++) f[j] = stgK[(g * 8 + j) * 260 + r];
#pragma unroll
            for (int j = 0; j < 8; j++) m[j] = smask[g * 8 + j];
            uint4 hv, lv;
#pragma unroll
            for (int j = 0; j < 8; j++) { f[j] *= m[j]; skacc += f[j]; }
            cvt2(f[0], f[1], hv.x, lv.x);
            cvt2(f[2], f[3], hv.y, lv.y);
            cvt2(f[4], f[5], hv.z, lv.z);
            cvt2(f[6], f[7], hv.w, lv.w);
            u32 tb = (u32)(r >> 7) * 16384;
            u32 sw = sw64((u32)((r & 127) * 64 + g * 16));
            *(uint4*)(smem + K1_OPS + s * OPSET + tb + sw) = hv;
            *(uint4*)(smem + K1_OPS + s * OPSET + tb + 8192 + sw) = lv;
        }
        // ---- B: raw value, 256 e-rows x 32 n ----
#pragma unroll
        for (int k = 0; k < 2; k++) {
            int i = tid + 512 * k;
            int r = i & 255, g = i >> 8;
            float f[8], m[8];
#pragma unroll
            for (int j = 0; j < 8; j++) f[j] = stgV[(g * 8 + j) * 260 + r];
#pragma unroll
            for (int j = 0; j < 8; j++) m[j] = smask[g * 8 + j];
            uint4 hv, lv;
#pragma unroll
            for (int j = 0; j < 8; j++) svacc += m[j] * f[j];
            cvt2(f[0], f[1], hv.x, lv.x);
            cvt2(f[2], f[3], hv.y, lv.y);
            cvt2(f[4], f[5], hv.z, lv.z);
            cvt2(f[6], f[7], hv.w, lv.w);
            u32 sw = sw64((u32)(r * 64 + g * 16));
            *(uint4*)(smem + K1_OPS + s * OPSET + 32768 + sw) = hv;
            *(uint4*)(smem + K1_OPS + s * OPSET + 49152 + sw) = lv;
        }
        __syncthreads();                    // converts done: staging free, ops ready
        if (c < 15) { stage_issue(c + 1); cp_commit(); }   // overlaps MMA(c)
        fence_async_proxy();
        if (wid == 0 && elect1()) {
            const ull dBH = mk_desc64(ops + 32768), dBL = mk_desc64(ops + 49152);
#pragma unroll
            for (int t = 0; t < 2; t++) {
                const ull aH = mk_desc64(ops + t * 16384);
                const ull aL = mk_desc64(ops + t * 16384 + 8192);
                const u32 dt = tbase + t * 256;
#pragma unroll
                for (int ks = 0; ks < 2; ks++) {
                    ull o = (ull)(ks * 2);
                    mma_f16_ss(dt, aH + o, dBH + o, MMA_IDESC, !(c == 0 && ks == 0));
                    mma_f16_ss(dt, aH + o, dBL + o, MMA_IDESC, 1);
                    mma_f16_ss(dt, aL + o, dBH + o, MMA_IDESC, 1);
                }
            }
            mma_commit(sb + (s ? MB1 : MB0));
        }
    }
    mbar_wait(sb + MB0, 1);   // 8 commits each -> final parity 1
    mbar_wait(sb + MB1, 1);
    tc_fence_after();

    if (wid < 8) {
        const int t = wid >> 2, w4 = wid & 3;
        float* dst0 = g_S + ((size_t)b * D_ + t * 128 + w4 * 32 + lid) * D_;
#pragma unroll
        for (int blk = 0; blk < 8; blk++) {
            u32 r[32];
            LDTM32(r, tbase + t * 256 + blk * 32);
            tmem_wait_ld();
#pragma unroll
            for (int cc = 0; cc < 32; cc++)
                atomicAdd(dst0 + blk * 32 + cc, __uint_as_float(r[cc]));
        }
    }
    __syncthreads();
    float* sredA = (float*)(smem + K1_OPS);   // opsets free now
    float* sredB = sredA + 512;
    sredA[tid] = skacc;
    sredB[tid] = svacc;
    __syncthreads();
    if (tid < 256) {
        atomicAdd(&g_rk[b * D_ + tid], sredA[tid] + sredA[tid + 256]);
        atomicAdd(&g_rv[b * D_ + tid], sredB[tid] + sredB[tid + 256]);
    }
    __syncthreads();
    if (tid == 0) { mbar_inval(sb + MB0); mbar_inval(sb + MB1); }
    __syncthreads();
    if (wid == 0) tmem_dealloc(tbase, 512);
#else
    // FFMA fallback (non-'a' PTX stage only)
    const int tid = threadIdx.x;
    const int b = blockIdx.y, chunk = blockIdx.x;
    const int n_start = chunk * 512;
    for (int idx = tid; idx < 256 * 256; idx += 512) {
        int d = idx >> 8, e = idx & 255;
        float acc = 0.f;
        for (int n = n_start; n < n_start + 512; n++) {
            float m = g_m[(size_t)b * N_ + n];
            acc += m * key[((size_t)b * N_ + n) * D_ + d] * value[((size_t)b * N_ + n) * D_ + e];
        }
        atomicAdd(&g_S[((size_t)b * D_ + d) * D_ + e], acc);
    }
    if (tid < 256) {
        float sk = 0.f, sv = 0.f;
        for (int n = n_start; n < n_start + 512; n++) {
            float m = g_m[(size_t)b * N_ + n];
            sk += m * key[((size_t)b * N_ + n) * D_ + tid];
            sv += m * value[((size_t)b * N_ + n) * D_ + tid];
        }
        atomicAdd(&g_rk[b * D_ + tid], sk);
        atomicAdd(&g_rv[b * D_ + tid], sv);
    }
#endif
}

// ---------------- k_uw: u = Wk@rk, w = Wv@rv ----------------
__global__ void k_uw(const float* __restrict__ Wk, const float* __restrict__ Wv) {
    int b = blockIdx.x, d = threadIdx.x;
    float su = 0.f, sw = 0.f;
    for (int i = 0; i < D_; i++) {
        su += Wk[d * D_ + i] * g_rk[b * D_ + i];
        sw += Wv[d * D_ + i] * g_rv[b * D_ + i];
    }
    g_u[b * D_ + d] = su;
    g_w[b * D_ + d] = sw;
}

// ---------------- k2: T1 = Wk @ S ----------------
__global__ void __launch_bounds__(256, 1)
k2_T1(const float* __restrict__ Wk) {
    const int b = blockIdx.y, d0 = blockIdx.x * 16;
    const int tid = threadIdx.x, tx = tid & 15, ty = tid >> 4;
    __shared__ float sA[16][16];
    __shared__ float sB[16][256];
    ull acc[8];
#pragma unroll
    for (int p = 0; p < 8; p++) acc[p] = 0ull;
    const float* Sb = g_S + b * D_ * D_;
    for (int i0 = 0; i0 < D_; i0 += 16) {
        __syncthreads();
        if (tid < 64) {
            int r = tid >> 2, q = tid & 3;
            *(float4*)&sA[r][q * 4] = *(const float4*)(Wk + (size_t)(d0 + r) * D_ + i0 + q * 4);
        }
#pragma unroll
        for (int i = 0; i < 4; i++) {
            int idx = tid + 256 * i;
            int r = idx >> 6, q = idx & 63;
            *(float4*)&sB[r][q * 4] = *(const float4*)(Sb + (size_t)(i0 + r) * D_ + q * 4);
        }
        __syncthreads();
#pragma unroll
        for (int ii = 0; ii < 16; ii++) {
            float a = sA[ty][ii];
            ull a2 = pack2(a, a);
#pragma unroll
            for (int p = 0; p < 8; p++)
                acc[p] = ffma2(a2, *(const ull*)&sB[ii][2 * tx + 32 * p], acc[p]);
        }
    }
    float* T1b = g_T1 + b * D_ * D_;
    int row = d0 + ty;
#pragma unroll
    for (int p = 0; p < 8; p++) {
        float lo, hi; unpack2(acc[p], lo, hi);
        *(float2*)&T1b[row * D_ + 2 * tx + 32 * p] = make_float2(lo, hi);
    }
}

// ---------------- k3: A = (T1 @ Wv^T + rank-1) / sqrt(8) ----------------
__global__ void __launch_bounds__(256, 1)
k3_A(const float* __restrict__ Wv, const float* __restrict__ bk,
     const float* __restrict__ bv) {
    const int b = blockIdx.y, d0 = blockIdx.x * 16;
    const int tid = threadIdx.x, tx = tid & 15, ty = tid >> 4;
    __shared__ float sA[16][16];
    __shared__ float sB[16][258];
    ull acc[8];
#pragma unroll
    for (int p = 0; p < 8; p++) acc[p] = 0ull;
    const float* T1b = g_T1 + b * D_ * D_;
    for (int j0 = 0; j0 < D_; j0 += 16) {
        __syncthreads();
        if (tid < 64) {
            int r = tid >> 2, q = tid & 3;
            *(float4*)&sA[r][q * 4] = *(const float4*)(T1b + (size_t)(d0 + r) * D_ + j0 + q * 4);
        }
#pragma unroll
        for (int i = 0; i < 4; i++) {
            int idx = tid + 256 * i;
            int q = idx & 3, e = idx >> 2;
            float4 v = *(const float4*)(Wv + (size_t)e * D_ + j0 + q * 4);
            sB[q * 4 + 0][e] = v.x; sB[q * 4 + 1][e] = v.y;
            sB[q * 4 + 2][e] = v.z; sB[q * 4 + 3][e] = v.w;
        }
        __syncthreads();
#pragma unroll
        for (int jj = 0; jj < 16; jj++) {
            float a = sA[ty][jj];
            ull a2 = pack2(a, a);
#pragma unroll
            for (int p = 0; p < 8; p++)
                acc[p] = ffma2(a2, *(const ull*)&sB[jj][2 * tx + 32 * p], acc[p]);
        }
    }
    const int d = d0 + ty;
    const float u_d = g_u[b * D_ + d], bk_d = bk[d], cmv = g_cm[b];
    const float inv = 0.3535533905932738f;
    float* Ab = g_A + b * D_ * D_;
#pragma unroll
    for (int p = 0; p < 8; p++) {
        float lo, hi; unpack2(acc[p], lo, hi);
        int e = 2 * tx + 32 * p;
        float bv0 = bv[e], bv1 = bv[e + 1];
        float w0 = g_w[b * D_ + e], w1 = g_w[b * D_ + e + 1];
        lo = (lo + u_d * bv0 + bk_d * w0 + cmv * bk_d * bv0) * inv;
        hi = (hi + u_d * bv1 + bk_d * w1 + cmv * bk_d * bv1) * inv;
        *(float2*)&Ab[d * D_ + e] = make_float2(lo, hi);
    }
}

// ---------------- k4: column softmax + t = bq^T aw ----------------
__global__ void k4_softmax(const float* __restrict__ bq) {
    const int b = blockIdx.y;
    const int w = threadIdx.x >> 5, lane = threadIdx.x & 31;
    const int e = blockIdx.x * 8 + w;
    float* col = g_A + b * D_ * D_ + e;
    float v[8];
#pragma unroll
    for (int s = 0; s < 8; s++) v[s] = col[(lane + 32 * s) * D_];
    float mx = v[0];
#pragma unroll
    for (int s = 1; s < 8; s++) mx = fmaxf(mx, v[s]);
#pragma unroll
    for (int o = 16; o > 0; o >>= 1) mx = fmaxf(mx, __shfl_xor_sync(0xffffffffu, mx, o));
    float sum = 0.f;
#pragma unroll
    for (int s = 0; s < 8; s++) { v[s] = expf(v[s] - mx); sum += v[s]; }
#pragma unroll
    for (int o = 16; o > 0; o >>= 1) sum += __shfl_xor_sync(0xffffffffu, sum, o);
    const float isum = 1.f / sum;
    float tacc = 0.f;
#pragma unroll
    for (int s = 0; s < 8; s++) {
        float p = v[s] * isum;
        col[(lane + 32 * s) * D_] = p;
        tacc += p * bq[lane + 32 * s];
    }
#pragma unroll
    for (int o = 16; o > 0; o >>= 1) tacc += __shfl_xor_sync(0xffffffffu, tacc, o);
    if (lane == 0) g_t[b * D_ + e] = tacc;
}

// ---------------- k5: M^T[e][i] = sum_d Wq[d][i] aw[d][e] -> bf16 hi/lo ------
__global__ void __launch_bounds__(256, 1)
k5_M(const float* __restrict__ Wq) {
    const int b = blockIdx.y, i0 = blockIdx.x * 16;
    const int tid = threadIdx.x, tx = tid & 15, ty = tid >> 4;
    __shared__ float sA[16][17];
    __shared__ float sB[16][256];
    ull acc[8];
#pragma unroll
    for (int p = 0; p < 8; p++) acc[p] = 0ull;
    const float* awb = g_A + b * D_ * D_;
    for (int dd0 = 0; dd0 < D_; dd0 += 16) {
        __syncthreads();
        if (tid < 64) {
            int r = tid >> 2, q = tid & 3;
            float4 v = *(const float4*)(Wq + (size_t)(dd0 + r) * D_ + i0 + q * 4);
            sA[q * 4 + 0][r] = v.x; sA[q * 4 + 1][r] = v.y;
            sA[q * 4 + 2][r] = v.z; sA[q * 4 + 3][r] = v.w;
        }
#pragma unroll
        for (int i = 0; i < 4; i++) {
            int idx = tid + 256 * i;
            int r = idx >> 6, q = idx & 63;
            *(float4*)&sB[r][q * 4] = *(const float4*)(awb + (size_t)(dd0 + r) * D_ + q * 4);
        }
        __syncthreads();
#pragma unroll
        for (int dd = 0; dd < 16; dd++) {
            float a = sA[ty][dd];
            ull a2 = pack2(a, a);
#pragma unroll
            for (int p = 0; p < 8; p++)
                acc[p] = ffma2(a2, *(const ull*)&sB[dd][2 * tx + 32 * p], acc[p]);
        }
    }
    const int row = i0 + ty;
#pragma unroll
    for (int p = 0; p < 8; p++) {
        float lo, hi; unpack2(acc[p], lo, hi);
        int e0 = 2 * tx + 32 * p, e1 = e0 + 1;
        __nv_bfloat16 h0 = __float2bfloat16(lo);
        __nv_bfloat16 h1 = __float2bfloat16(hi);
        g_MTH[((size_t)b * D_ + e0) * D_ + row] = h0;
        g_MTL[((size_t)b * D_ + e0) * D_ + row] = __float2bfloat16(lo - __bfloat162float(h0));
        g_MTH[((size_t)b * D_ + e1) * D_ + row] = h1;
        g_MTL[((size_t)b * D_ + e1) * D_ + row] = __float2bfloat16(hi - __bfloat162float(h1));
    }
}

// ---------------- k6: out = query @ M + t, 2 n-tiles per CTA -----------------
// grid (32, B), 512 threads. 8 windows of K=32 SW64, shared B, reg-prefetched A.
__global__ void __launch_bounds__(512, 1)
k6_mma(const float* __restrict__ query, float* __restrict__ out) {
#if TCOK
    extern __shared__ char smem[];
    const u32 sb = smem_u32(smem);
    const int tid = threadIdx.x, wid = tid >> 5, lid = tid & 31;
    const int b = blockIdx.y, n0 = blockIdx.x * 256;

    if (wid == 0) { tmem_alloc(sb + SM_TPTR, 512); tmem_relinquish(); }
    if (tid == 0) { mbar_init(sb + MB0, 1); mbar_init(sb + MB1, 1); }
    __syncthreads();
    u32 tbase;
    asm volatile("ld.shared.b32 %0, [%1];" : "=r"(tbase) : "r"(sb + SM_TPTR));

    const float* qb = query + ((size_t)b * N_ + n0) * D_;
    const size_t bbase0 = (size_t)b * D_ * D_;

    // fixed per-thread A geometry (both slots)
    int tA[2], swA[2];
    const float* qsrc[2];
    {
#pragma unroll
        for (int k = 0; k < 2; k++) {
            int i = tid + 512 * k;
            int t = i >> 9, idx = i & 511;
            int rA = idx >> 2, gA = idx & 3;
            tA[k] = t;
            swA[k] = (int)sw64((u32)(rA * 64 + gA * 16));
            qsrc[k] = qb + ((size_t)(t * 128 + rA)) * D_ + gA * 8;
        }
    }

    for (int c = 0; c < 8; c++) {
        const int s = c & 1;
        const int dc = c * 32;
        const u32 ops = sb + SM_OPS + s * OPSET;

        // prefetch A q values into regs (LDGs issue before mbar wait)
        float4 pa[2], pb[2];
#pragma unroll
        for (int k = 0; k < 2; k++) {
            pa[k] = *(const float4*)(qsrc[k] + dc);
            pb[k] = *(const float4*)(qsrc[k] + dc + 4);
        }
        if (c >= 2) mbar_wait(sb + (s ? MB1 : MB0), ((c >> 1) - 1) & 1);

        // B: M^T rows via cp.async directly into swizzled operands
#pragma unroll
        for (int k = 0; k < 2; k++) {
            int i = tid + 512 * k;
            int r = i >> 2, g = i & 3;
            size_t off = bbase0 + (size_t)r * D_ + dc + g * 8;
            u32 sw = sw64((u32)(r * 64 + g * 16));
            cp16(ops + 32768 + sw, g_MTH + off);
            cp16(ops + 49152 + sw, g_MTL + off);
        }
        cp_commit();
        // A: convert prefetched regs -> hi/lo
#pragma unroll
        for (int k = 0; k < 2; k++) {
            uint4 hv, lv;
            cvt2(pa[k].x, pa[k].y, hv.x, lv.x);
            cvt2(pa[k].z, pa[k].w, hv.y, lv.y);
            cvt2(pb[k].x, pb[k].y, hv.z, lv.z);
            cvt2(pb[k].z, pb[k].w, hv.w, lv.w);
            *(uint4*)(smem + SM_OPS + s * OPSET + tA[k] * 16384 + swA[k]) = hv;
            *(uint4*)(smem + SM_OPS + s * OPSET + tA[k] * 16384 + 8192 + swA[k]) = lv;
        }
        cp_wait<0>();
        __syncthreads();
        fence_async_proxy();
        if (wid == 0 && elect1()) {
            const ull dBH = mk_desc64(ops + 32768), dBL = mk_desc64(ops + 49152);
#pragma unroll
            for (int t = 0; t < 2; t++) {
                const ull aH = mk_desc64(ops + t * 16384);
                const ull aL = mk_desc64(ops + t * 16384 + 8192);
                const u32 dt = tbase + t * 256;
#pragma unroll
                for (int ks = 0; ks < 2; ks++) {
                    ull o = (ull)(ks * 2);
                    mma_f16_ss(dt, aH + o, dBH + o, MMA_IDESC, !(c == 0 && ks == 0));
                    mma_f16_ss(dt, aH + o, dBL + o, MMA_IDESC, 1);
                    mma_f16_ss(dt, aL + o, dBH + o, MMA_IDESC, 1);
                }
            }
            mma_commit(sb + (s ? MB1 : MB0));
        }
    }
    mbar_wait(sb + MB0, 1);   // 4 commits each -> final parity 1
    mbar_wait(sb + MB1, 1);
    tc_fence_after();

    float* stage = (float*)(smem + SM_OPS);   // [2][128][68] (opsets free)
    for (int cb = 0; cb < 4; cb++) {
        __syncthreads();
        if (wid < 8) {
            const int t = wid >> 2, w4 = wid & 3;
            u32 r0a[32], r1a[32];
            LDTM32(r0a, tbase + t * 256 + cb * 64);
            LDTM32(r1a, tbase + t * 256 + cb * 64 + 32);
            tmem_wait_ld();
            float* srow = stage + (size_t)t * 128 * 68 + (w4 * 32 + lid) * 68;
#pragma unroll
            for (int cc = 0; cc < 32; cc++) {
                srow[cc] = __uint_as_float(r0a[cc]);
                srow[32 + cc] = __uint_as_float(r1a[cc]);
            }
        }
        __syncthreads();
#pragma unroll
        for (int k = 0; k < 8; k++) {
            int i = tid + 512 * k;
            int t = i >> 11, j = i & 2047;
            int r = j >> 4, c4 = j & 15;
            float4 v = *(float4*)(stage + (size_t)t * 128 * 68 + r * 68 + c4 * 4);
            int e = cb * 64 + c4 * 4;
            v.x += g_t[b * D_ + e];
            v.y += g_t[b * D_ + e + 1];
            v.z += g_t[b * D_ + e + 2];
            v.w += g_t[b * D_ + e + 3];
            *(float4*)(out + ((size_t)b * N_ + n0 + t * 128 + r) * D_ + e) = v;
        }
    }
    __syncthreads();
    if (tid == 0) { mbar_inval(sb + MB0); mbar_inval(sb + MB1); }
    __syncthreads();
    if (wid == 0) tmem_dealloc(tbase, 512);
#else
    // FFMA fallback
    const int tid = threadIdx.x;
    const int b = blockIdx.y, n0 = blockIdx.x * 256;
    for (int idx = tid; idx < 256 * 256; idx += 512) {
        int n = n0 + (idx >> 8), e = idx & 255;
        const float* q = query + ((size_t)b * N_ + n) * D_;
        const __nv_bfloat16* mh = g_MTH + ((size_t)b * D_ + e) * D_;
        const __nv_bfloat16* ml = g_MTL + ((size_t)b * D_ + e) * D_;
        float acc = g_t[b * D_ + e];
        for (int d = 0; d < D_; d++)
            acc += q[d] * (__bfloat162float(mh[d]) + __bfloat162float(ml[d]));
        out[((size_t)b * N_ + n) * D_ + e] = acc;
    }
#endif
}

// ---------------- launch ----------------
extern "C" void kernel_launch(void* const* d_in, const int* in_sizes, int n_in,
                              void* d_out, int out_size) {
    const float* query = (const float*)d_in[0];
    const float* key   = (const float*)d_in[1];
    const float* value = (const float*)d_in[2];
    const void*  maskraw = d_in[3];
    int o = (n_in >= 11) ? 5 : 4;
    const float* Wq = (const float*)d_in[o + 0];
    const float* bq = (const float*)d_in[o + 1];
    const float* Wk = (const float*)d_in[o + 2];
    const float* bk = (const float*)d_in[o + 3];
    const float* Wv = (const float*)d_in[o + 4];
    const float* bv = (const float*)d_in[o + 5];
    float* out = (float*)d_out;
    (void)in_sizes; (void)out_size;

    cudaFuncSetAttribute(k1_mma, cudaFuncAttributeMaxDynamicSharedMemorySize, K1_TOTAL);
    cudaFuncSetAttribute(k6_mma, cudaFuncAttributeMaxDynamicSharedMemorySize, K6_TOTAL);

    k_zero<<<(B_ * D_ * D_ + 255) / 256, 256>>>();
    k_detect<<<64, 256>>>((const unsigned char*)maskraw);
    k_maskconv<<<(B_ * N_) / 256, 256>>>(maskraw);
    k1_mma<<<dim3(16, B_), 512, K1_TOTAL>>>(key, value);
    k_uw<<<B_, 256>>>(Wk, Wv);
    k2_T1<<<dim3(16, B_), 256>>>(Wk);
    k3_A<<<dim3(16, B_), 256>>>(Wv, bk, bv);
    k4_softmax<<<dim3(32, B_), 256>>>(bq);
    k5_M<<<dim3(16, B_), 256>>>(Wq);
    k6_mma<<<dim3(32, B_), 512, K6_TOTAL>>>(query, out);
}

// round 14
// speedup vs baseline: 1.0409x; 1.0409x over previous
#include <cuda_runtime.h>
#include <cuda_bf16.h>
#include <cstdint>
#include <cstddef>

#define B_ 8
#define N_ 8192
#define D_ 256

typedef unsigned long long ull;
typedef unsigned int u32;

#if !defined(__CUDA_ARCH__) || defined(__CUDA_ARCH_FEAT_SM103_ALL) || defined(__CUDA_ARCH_FEAT_SM100_ALL) || defined(__CUDA_ARCH_FEAT_SM101_ALL)
#define TCOK 1
#else
#define TCOK 0
#endif

// ---------------- device scratch ----------------
__device__ __nv_bfloat16 g_MTH[B_ * D_ * D_];   // (Wq^T aw)^T hi [b][e][i]
__device__ __nv_bfloat16 g_MTL[B_ * D_ * D_];
__device__ float g_S[B_ * D_ * D_];
__device__ float g_A[B_ * D_ * D_];
__device__ float g_rk[B_ * D_];
__device__ float g_rv[B_ * D_];
__device__ float g_u[B_ * D_];
__device__ float g_w[B_ * D_];
__device__ float g_t[B_ * D_];
__device__ float g_cm[B_];
__device__ int   g_kind;
__device__ float g_m[B_ * N_];

// ---------------- scalar helpers ----------------
__device__ __forceinline__ ull pack2(float lo, float hi) {
    ull r; asm("mov.b64 %0, {%1,%2};" : "=l"(r) : "f"(lo), "f"(hi)); return r;
}
__device__ __forceinline__ void unpack2(ull v, float& lo, float& hi) {
    asm("mov.b64 {%0,%1}, %2;" : "=f"(lo), "=f"(hi) : "l"(v));
}
__device__ __forceinline__ ull ffma2(ull a, ull b, ull c) {
    ull d; asm("fma.rn.f32x2 %0, %1, %2, %3;" : "=l"(d) : "l"(a), "l"(b), "l"(c)); return d;
}
__device__ __forceinline__ u32 prmt7632(u32 a, u32 b) {
    u32 d; asm("prmt.b32 %0, %1, %2, 0x7632;" : "=r"(d) : "r"(a), "r"(b)); return d;
}
// f32 pair -> bf16x2 hi (truncated) + bf16x2 lo (residual, truncated). err ~2^-16.
__device__ __forceinline__ void cvt2(float x0, float x1, u32& h2, u32& l2) {
    u32 u0 = __float_as_uint(x0), u1 = __float_as_uint(x1);
    h2 = prmt7632(u0, u1);
    float l0 = x0 - __uint_as_float(u0 & 0xFFFF0000u);
    float l1 = x1 - __uint_as_float(u1 & 0xFFFF0000u);
    l2 = prmt7632(__float_as_uint(l0), __float_as_uint(l1));
}

// ---------------- tcgen05 / async helpers (guarded) ----------------
#if TCOK
__device__ __forceinline__ u32 smem_u32(const void* p) {
    u32 a; asm("{ .reg .u64 t; cvta.to.shared.u64 t, %1; cvt.u32.u64 %0, t; }" : "=r"(a) : "l"(p));
    return a;
}
__device__ __forceinline__ int elect1() {
    u32 p;
    asm volatile("{\n\t.reg .pred p;\n\telect.sync _|p, 0xFFFFFFFF;\n\tselp.b32 %0, 1, 0, p;\n\t}" : "=r"(p));
    return (int)p;
}
__device__ __forceinline__ void cp16(u32 dst, const void* src) {
    asm volatile("cp.async.cg.shared.global [%0], [%1], 16;" :: "r"(dst), "l"(src) : "memory");
}
__device__ __forceinline__ void cp_commit() {
    asm volatile("cp.async.commit_group;" ::: "memory");
}
template <int N>
__device__ __forceinline__ void cp_wait() {
    asm volatile("cp.async.wait_group %0;" :: "n"(N) : "memory");
}
__device__ __forceinline__ void mbar_init(u32 mbar, u32 cnt) {
    asm volatile("mbarrier.init.shared.b64 [%0], %1;" :: "r"(mbar), "r"(cnt) : "memory");
}
__device__ __forceinline__ void mbar_inval(u32 mbar) {
    asm volatile("mbarrier.inval.shared.b64 [%0];" :: "r"(mbar) : "memory");
}
__device__ __forceinline__ void mbar_wait(u32 mbar, u32 parity) {
    asm volatile(
        "{\n\t.reg .pred P;\n\t"
        "WL_%=:\n\t"
        "mbarrier.try_wait.parity.acquire.cta.shared::cta.b64 P, [%0], %1, 0x989680;\n\t"
        "@P bra WD_%=;\n\t"
        "bra.uni WL_%=;\n\t"
        "WD_%=:\n\t}"
        :: "r"(mbar), "r"(parity) : "memory");
}
__device__ __forceinline__ void tmem_alloc(u32 smem_dst, u32 ncols) {
    asm volatile("tcgen05.alloc.cta_group::1.sync.aligned.shared::cta.b32 [%0], %1;"
                 :: "r"(smem_dst), "r"(ncols) : "memory");
}
__device__ __forceinline__ void tmem_relinquish() {
    asm volatile("tcgen05.relinquish_alloc_permit.cta_group::1.sync.aligned;");
}
__device__ __forceinline__ void tmem_dealloc(u32 tmem, u32 ncols) {
    asm volatile("tcgen05.dealloc.cta_group::1.sync.aligned.b32 %0, %1;" :: "r"(tmem), "r"(ncols));
}
__device__ __forceinline__ void mma_f16_ss(u32 d_tmem, ull a_desc, ull b_desc, u32 idesc, int accum) {
    u32 z = 0;
    asm volatile(
        "{\n\t.reg .pred p;\n\tsetp.ne.u32 p, %5, 0;\n\t"
        "tcgen05.mma.cta_group::1.kind::f16 [%0], %1, %2, %3, {%4, %4, %4, %4}, p;\n\t}"
        :: "r"(d_tmem), "l"(a_desc), "l"(b_desc), "r"(idesc), "r"(z), "r"((u32)accum) : "memory");
}
__device__ __forceinline__ void mma_commit(u32 mbar) {
    asm volatile("tcgen05.commit.cta_group::1.mbarrier::arrive::one.shared::cluster.b64 [%0];"
                 :: "r"(mbar) : "memory");
}
__device__ __forceinline__ void fence_async_proxy() {
    asm volatile("fence.proxy.async.shared::cta;" ::: "memory");
}
__device__ __forceinline__ void tc_fence_after() {
    asm volatile("tcgen05.fence::after_thread_sync;" ::: "memory");
}
__device__ __forceinline__ void tmem_wait_ld() {
    asm volatile("tcgen05.wait::ld.sync.aligned;" ::: "memory");
}

#define LDTM32(r, addr)                                                      \
    asm volatile("tcgen05.ld.sync.aligned.32x32b.x32.b32 "                   \
        "{%0, %1, %2, %3, %4, %5, %6, %7, %8, %9, %10, %11, %12, %13, %14, %15, " \
        " %16, %17, %18, %19, %20, %21, %22, %23, %24, %25, %26, %27, %28, %29, %30, %31}, [%32];" \
        : "=r"((r)[0]), "=r"((r)[1]), "=r"((r)[2]), "=r"((r)[3]),            \
          "=r"((r)[4]), "=r"((r)[5]), "=r"((r)[6]), "=r"((r)[7]),            \
          "=r"((r)[8]), "=r"((r)[9]), "=r"((r)[10]), "=r"((r)[11]),          \
          "=r"((r)[12]), "=r"((r)[13]), "=r"((r)[14]), "=r"((r)[15]),        \
          "=r"((r)[16]), "=r"((r)[17]), "=r"((r)[18]), "=r"((r)[19]),        \
          "=r"((r)[20]), "=r"((r)[21]), "=r"((r)[22]), "=r"((r)[23]),        \
          "=r"((r)[24]), "=r"((r)[25]), "=r"((r)[26]), "=r"((r)[27]),        \
          "=r"((r)[28]), "=r"((r)[29]), "=r"((r)[30]), "=r"((r)[31])         \
        : "r"(addr))

__device__ __forceinline__ u32 sw64(u32 off)  { return off ^ ((off >> 3) & 0x30); }

#define DESC_BASE64 ((4ull << 61) | (1ull << 46) | (32ull << 32) | (1ull << 16))
__device__ __forceinline__ ull mk_desc64(u32 addr) { return DESC_BASE64 | ((ull)(addr >> 4) & 0x3FFF); }

#define MMA_IDESC 0x8400490u   // F32 accum, BF16xBF16, M=128, N=256
#endif  // TCOK

// ---- k1 layout: hdr | masks (2KB) | 2x opset ----
#define SM_TPTR 0
#define MB0 8
#define MB1 16
#define SM_MASKS 128                    // 512 floats
#define K1_OPS 4096
#define OPSET 65536                     // A0H 8K|A0L 8K|A1H 8K|A1L 8K|BH 16K|BL 16K
#define K1_TOTAL (K1_OPS + 2 * OPSET)   // 135168

// ---- k6 layout ----
#define SM_OPS 1024
#define K6_TOTAL (1024 + 2 * OPSET)     // 132096

// ---------------- mask detect + canonicalize (+cm) ----------------
__global__ void k_detect(const unsigned char* __restrict__ raw) {
    int idx = blockIdx.x * blockDim.x + threadIdx.x;   // < 16384
    if (raw[idx * 4 + 1] != 0) atomicOr(&g_kind, 1);
}

__global__ void k_maskconv(const void* __restrict__ rawv) {
    int n = blockIdx.x * blockDim.x + threadIdx.x;
    bool padded;
    if (g_kind) padded = ((const unsigned char*)rawv)[n] != 0;
    else        padded = ((const unsigned int*)rawv)[n] != 0u;
    float m = padded ? 0.f : 1.f;
    g_m[n] = m;
    float s = m;
#pragma unroll
    for (int o = 16; o > 0; o >>= 1) s += __shfl_xor_sync(0xffffffffu, s, o);
    __shared__ float red[8];
    int wid = threadIdx.x >> 5, lane = threadIdx.x & 31;
    if (lane == 0) red[wid] = s;
    __syncthreads();
    if (threadIdx.x == 0) {
        float t = 0.f;
        for (int i = 0; i < 8; i++) t += red[i];
        atomicAdd(&g_cm[n >> 13], t);
    }
}

__global__ void k_zero() {
    int i = blockIdx.x * blockDim.x + threadIdx.x;
    if (i < B_ * D_ * D_) g_S[i] = 0.f;
    if (i < B_ * D_) { g_rk[i] = 0.f; g_rv[i] = 0.f; }
    if (i < B_) g_cm[i] = 0.f;
    if (i == 0) g_kind = 0;
}

// ---------------- k1: S[b] = K_m^T V, reg-double-buffered direct LDG ---------
// grid (16 chunks, B), 512 threads, single wave. 16 windows of n=32, K=32 SW64.
__global__ void __launch_bounds__(512, 1)
k1_mma(const float* __restrict__ key, const float* __restrict__ value) {
#if TCOK
    extern __shared__ char smem[];
    const u32 sb = smem_u32(smem);
    const int tid = threadIdx.x, wid = tid >> 5, lid = tid & 31;
    const int b = blockIdx.y, chunk = blockIdx.x;
    const int n_start = chunk * 512;

    if (wid == 0) { tmem_alloc(sb + SM_TPTR, 512); tmem_relinquish(); }
    if (tid == 0) { mbar_init(sb + MB0, 1); mbar_init(sb + MB1, 1); }
    float* smask = (float*)(smem + SM_MASKS);
    smask[tid] = g_m[(size_t)b * N_ + n_start + tid];     // whole-chunk masks
    __syncthreads();
    u32 tbase;
    asm volatile("ld.shared.b32 %0, [%1];" : "=r"(tbase) : "r"(sb + SM_TPTR));

    // per-thread fixed slot geometry (A and B share the mapping)
    int rS[2], gS[2];
    const float* kb_[2];
    const float* vb_[2];
    u32 swS[2], tbS[2];
#pragma unroll
    for (int k = 0; k < 2; k++) {
        int i = tid + 512 * k;
        rS[k] = i & 255; gS[k] = i >> 8;                  // g 0..3
        kb_[k] = key + ((size_t)b * N_ + n_start + gS[k] * 8) * D_ + rS[k];
        vb_[k] = value + ((size_t)b * N_ + n_start + gS[k] * 8) * D_ + rS[k];
        swS[k] = sw64((u32)((rS[k] & 127) * 64 + gS[k] * 16));
        tbS[k] = (u32)(rS[k] >> 7) * 16384;
    }

    float fA[2][8], fB[2][8];
#pragma unroll
    for (int k = 0; k < 2; k++)
#pragma unroll
        for (int j = 0; j < 8; j++) {
            fA[k][j] = kb_[k][(size_t)j * D_];
            fB[k][j] = vb_[k][(size_t)j * D_];
        }

    float skacc = 0.f, svacc = 0.f;

    for (int c = 0; c < 16; c++) {
        const int s = c & 1;
        const u32 ops = sb + K1_OPS + s * OPSET;
        if (c >= 2) mbar_wait(sb + (s ? MB1 : MB0), ((c >> 1) - 1) & 1);

        // ---- A: masked key -> two M=128 tiles; then reload regs for c+1 ----
#pragma unroll
        for (int k = 0; k < 2; k++) {
            const float* msk = smask + c * 32 + gS[k] * 8;
            float t[8];
#pragma unroll
            for (int j = 0; j < 8; j++) { t[j] = fA[k][j] * msk[j]; skacc += t[j]; }
            uint4 hv, lv;
            cvt2(t[0], t[1], hv.x, lv.x);
            cvt2(t[2], t[3], hv.y, lv.y);
            cvt2(t[4], t[5], hv.z, lv.z);
            cvt2(t[6], t[7], hv.w, lv.w);
            *(uint4*)(smem + K1_OPS + s * OPSET + tbS[k] + swS[k]) = hv;
            *(uint4*)(smem + K1_OPS + s * OPSET + tbS[k] + 8192 + swS[k]) = lv;
            if (c < 15) {
                const float* src = kb_[k] + (size_t)(c + 1) * 32 * D_;
#pragma unroll
                for (int j = 0; j < 8; j++) fA[k][j] = src[(size_t)j * D_];
            }
        }
        // ---- B: raw value; masked side sums; reload regs for c+1 ----
#pragma unroll
        for (int k = 0; k < 2; k++) {
            const float* msk = smask + c * 32 + gS[k] * 8;
#pragma unroll
            for (int j = 0; j < 8; j++) svacc += msk[j] * fB[k][j];
            uint4 hv, lv;
            cvt2(fB[k][0], fB[k][1], hv.x, lv.x);
            cvt2(fB[k][2], fB[k][3], hv.y, lv.y);
            cvt2(fB[k][4], fB[k][5], hv.z, lv.z);
            cvt2(fB[k][6], fB[k][7], hv.w, lv.w);
            u32 sw = sw64((u32)(rS[k] * 64 + gS[k] * 16));
            *(uint4*)(smem + K1_OPS + s * OPSET + 32768 + sw) = hv;
            *(uint4*)(smem + K1_OPS + s * OPSET + 49152 + sw) = lv;
            if (c < 15) {
                const float* src = vb_[k] + (size_t)(c + 1) * 32 * D_;
#pragma unroll
                for (int j = 0; j < 8; j++) fB[k][j] = src[(size_t)j * D_];
            }
        }
        __syncthreads();
        fence_async_proxy();
        if (wid == 0 && elect1()) {
            const ull dBH = mk_desc64(ops + 32768), dBL = mk_desc64(ops + 49152);
#pragma unroll
            for (int t = 0; t < 2; t++) {
                const ull aH = mk_desc64(ops + t * 16384);
                const ull aL = mk_desc64(ops + t * 16384 + 8192);
                const u32 dt = tbase + t * 256;
#pragma unroll
                for (int ks = 0; ks < 2; ks++) {
                    ull o = (ull)(ks * 2);
                    mma_f16_ss(dt, aH + o, dBH + o, MMA_IDESC, !(c == 0 && ks == 0));
                    mma_f16_ss(dt, aH + o, dBL + o, MMA_IDESC, 1);
                    mma_f16_ss(dt, aL + o, dBH + o, MMA_IDESC, 1);
                }
            }
            mma_commit(sb + (s ? MB1 : MB0));
        }
    }
    mbar_wait(sb + MB0, 1);   // 8 commits each -> final parity 1
    mbar_wait(sb + MB1, 1);
    tc_fence_after();

    if (wid < 8) {
        const int t = wid >> 2, w4 = wid & 3;
        float* dst0 = g_S + ((size_t)b * D_ + t * 128 + w4 * 32 + lid) * D_;
#pragma unroll
        for (int blk = 0; blk < 8; blk++) {
            u32 r[32];
            LDTM32(r, tbase + t * 256 + blk * 32);
            tmem_wait_ld();
#pragma unroll
            for (int cc = 0; cc < 32; cc++)
                atomicAdd(dst0 + blk * 32 + cc, __uint_as_float(r[cc]));
        }
    }
    __syncthreads();
    float* sredA = (float*)(smem + K1_OPS);   // opsets free now
    float* sredB = sredA + 512;
    sredA[tid] = skacc;
    sredB[tid] = svacc;
    __syncthreads();
    if (tid < 256) {
        atomicAdd(&g_rk[b * D_ + tid], sredA[tid] + sredA[tid + 256]);
        atomicAdd(&g_rv[b * D_ + tid], sredB[tid] + sredB[tid + 256]);
    }
    __syncthreads();
    if (tid == 0) { mbar_inval(sb + MB0); mbar_inval(sb + MB1); }
    __syncthreads();
    if (wid == 0) tmem_dealloc(tbase, 512);
#else
    // FFMA fallback (non-'a' PTX stage only)
    const int tid = threadIdx.x;
    const int b = blockIdx.y, chunk = blockIdx.x;
    const int n_start = chunk * 512;
    for (int idx = tid; idx < 256 * 256; idx += 512) {
        int d = idx >> 8, e = idx & 255;
        float acc = 0.f;
        for (int n = n_start; n < n_start + 512; n++) {
            float m = g_m[(size_t)b * N_ + n];
            acc += m * key[((size_t)b * N_ + n) * D_ + d] * value[((size_t)b * N_ + n) * D_ + e];
        }
        atomicAdd(&g_S[((size_t)b * D_ + d) * D_ + e], acc);
    }
    if (tid < 256) {
        float sk = 0.f, sv = 0.f;
        for (int n = n_start; n < n_start + 512; n++) {
            float m = g_m[(size_t)b * N_ + n];
            sk += m * key[((size_t)b * N_ + n) * D_ + tid];
            sv += m * value[((size_t)b * N_ + n) * D_ + tid];
        }
        atomicAdd(&g_rk[b * D_ + tid], sk);
        atomicAdd(&g_rv[b * D_ + tid], sv);
    }
#endif
}

// ---------------- k_uw: u = Wk@rk, w = Wv@rv ----------------
__global__ void k_uw(const float* __restrict__ Wk, const float* __restrict__ Wv) {
    int b = blockIdx.x, d = threadIdx.x;
    float su = 0.f, sw = 0.f;
    for (int i = 0; i < D_; i++) {
        su += Wk[d * D_ + i] * g_rk[b * D_ + i];
        sw += Wv[d * D_ + i] * g_rv[b * D_ + i];
    }
    g_u[b * D_ + d] = su;
    g_w[b * D_ + d] = sw;
}

// ---------------- k23: T1 tile = Wk @ S (smem), then A = (T1 @ Wv^T + r1)/sqrt8
__global__ void __launch_bounds__(256, 1)
k23_TA(const float* __restrict__ Wk, const float* __restrict__ Wv,
       const float* __restrict__ bk, const float* __restrict__ bv) {
    const int b = blockIdx.y, d0 = blockIdx.x * 16;
    const int tid = threadIdx.x, tx = tid & 15, ty = tid >> 4;
    __shared__ float sA[16][16];
    __shared__ float sB[16][256];
    __shared__ float sT1[16][258];
    ull acc[8];
#pragma unroll
    for (int p = 0; p < 8; p++) acc[p] = 0ull;
    const float* Sb = g_S + b * D_ * D_;
    // phase 1: T1 rows d0..d0+15 = Wk[d0:,:] @ S
    for (int i0 = 0; i0 < D_; i0 += 16) {
        __syncthreads();
        if (tid < 64) {
            int r = tid >> 2, q = tid & 3;
            *(float4*)&sA[r][q * 4] = *(const float4*)(Wk + (size_t)(d0 + r) * D_ + i0 + q * 4);
        }
#pragma unroll
        for (int i = 0; i < 4; i++) {
            int idx = tid + 256 * i;
            int r = idx >> 6, q = idx & 63;
            *(float4*)&sB[r][q * 4] = *(const float4*)(Sb + (size_t)(i0 + r) * D_ + q * 4);
        }
        __syncthreads();
#pragma unroll
        for (int ii = 0; ii < 16; ii++) {
            float a = sA[ty][ii];
            ull a2 = pack2(a, a);
#pragma unroll
            for (int p = 0; p < 8; p++)
                acc[p] = ffma2(a2, *(const ull*)&sB[ii][2 * tx + 32 * p], acc[p]);
        }
    }
#pragma unroll
    for (int p = 0; p < 8; p++) {
        float lo, hi; unpack2(acc[p], lo, hi);
        sT1[ty][2 * tx + 32 * p] = lo;
        sT1[ty][2 * tx + 32 * p + 1] = hi;
    }
    __syncthreads();
    // phase 2: A tile = T1tile @ Wv^T
#pragma unroll
    for (int p = 0; p < 8; p++) acc[p] = 0ull;
    for (int j0 = 0; j0 < D_; j0 += 16) {
        __syncthreads();
#pragma unroll
        for (int i = 0; i < 4; i++) {
            int idx = tid + 256 * i;
            int q = idx & 3, e = idx >> 2;
            float4 v = *(const float4*)(Wv + (size_t)e * D_ + j0 + q * 4);
            sB[q * 4 + 0][e] = v.x; sB[q * 4 + 1][e] = v.y;
            sB[q * 4 + 2][e] = v.z; sB[q * 4 + 3][e] = v.w;
        }
        __syncthreads();
#pragma unroll
        for (int jj = 0; jj < 16; jj++) {
            float a = sT1[ty][j0 + jj];
            ull a2 = pack2(a, a);
#pragma unroll
            for (int p = 0; p < 8; p++)
                acc[p] = ffma2(a2, *(const ull*)&sB[jj][2 * tx + 32 * p], acc[p]);
        }
    }
    const int d = d0 + ty;
    const float u_d = g_u[b * D_ + d], bk_d = bk[d], cmv = g_cm[b];
    const float inv = 0.3535533905932738f;
    float* Ab = g_A + b * D_ * D_;
#pragma unroll
    for (int p = 0; p < 8; p++) {
        float lo, hi; unpack2(acc[p], lo, hi);
        int e = 2 * tx + 32 * p;
        float bv0 = bv[e], bv1 = bv[e + 1];
        float w0 = g_w[b * D_ + e], w1 = g_w[b * D_ + e + 1];
        lo = (lo + u_d * bv0 + bk_d * w0 + cmv * bk_d * bv0) * inv;
        hi = (hi + u_d * bv1 + bk_d * w1 + cmv * bk_d * bv1) * inv;
        *(float2*)&Ab[d * D_ + e] = make_float2(lo, hi);
    }
}

// ---------------- k4: column softmax + t = bq^T aw ----------------
__global__ void k4_softmax(const float* __restrict__ bq) {
    const int b = blockIdx.y;
    const int w = threadIdx.x >> 5, lane = threadIdx.x & 31;
    const int e = blockIdx.x * 8 + w;
    float* col = g_A + b * D_ * D_ + e;
    float v[8];
#pragma unroll
    for (int s = 0; s < 8; s++) v[s] = col[(lane + 32 * s) * D_];
    float mx = v[0];
#pragma unroll
    for (int s = 1; s < 8; s++) mx = fmaxf(mx, v[s]);
#pragma unroll
    for (int o = 16; o > 0; o >>= 1) mx = fmaxf(mx, __shfl_xor_sync(0xffffffffu, mx, o));
    float sum = 0.f;
#pragma unroll
    for (int s = 0; s < 8; s++) { v[s] = expf(v[s] - mx); sum += v[s]; }
#pragma unroll
    for (int o = 16; o > 0; o >>= 1) sum += __shfl_xor_sync(0xffffffffu, sum, o);
    const float isum = 1.f / sum;
    float tacc = 0.f;
#pragma unroll
    for (int s = 0; s < 8; s++) {
        float p = v[s] * isum;
        col[(lane + 32 * s) * D_] = p;
        tacc += p * bq[lane + 32 * s];
    }
#pragma unroll
    for (int o = 16; o > 0; o >>= 1) tacc += __shfl_xor_sync(0xffffffffu, tacc, o);
    if (lane == 0) g_t[b * D_ + e] = tacc;
}

// ---------------- k5: M^T[e][i] = sum_d Wq[d][i] aw[d][e] -> bf16 hi/lo ------
__global__ void __launch_bounds__(256, 1)
k5_M(const float* __restrict__ Wq) {
    const int b = blockIdx.y, i0 = blockIdx.x * 16;
    const int tid = threadIdx.x, tx = tid & 15, ty = tid >> 4;
    __shared__ float sA[16][17];
    __shared__ float sB[16][256];
    ull acc[8];
#pragma unroll
    for (int p = 0; p < 8; p++) acc[p] = 0ull;
    const float* awb = g_A + b * D_ * D_;
    for (int dd0 = 0; dd0 < D_; dd0 += 16) {
        __syncthreads();
        if (tid < 64) {
            int r = tid >> 2, q = tid & 3;
            float4 v = *(const float4*)(Wq + (size_t)(dd0 + r) * D_ + i0 + q * 4);
            sA[q * 4 + 0][r] = v.x; sA[q * 4 + 1][r] = v.y;
            sA[q * 4 + 2][r] = v.z; sA[q * 4 + 3][r] = v.w;
        }
#pragma unroll
        for (int i = 0; i < 4; i++) {
            int idx = tid + 256 * i;
            int r = idx >> 6, q = idx & 63;
            *(float4*)&sB[r][q * 4] = *(const float4*)(awb + (size_t)(dd0 + r) * D_ + q * 4);
        }
        __syncthreads();
#pragma unroll
        for (int dd = 0; dd < 16; dd++) {
            float a = sA[ty][dd];
            ull a2 = pack2(a, a);
#pragma unroll
            for (int p = 0; p < 8; p++)
                acc[p] = ffma2(a2, *(const ull*)&sB[dd][2 * tx + 32 * p], acc[p]);
        }
    }
    const int row = i0 + ty;
#pragma unroll
    for (int p = 0; p < 8; p++) {
        float lo, hi; unpack2(acc[p], lo, hi);
        int e0 = 2 * tx + 32 * p, e1 = e0 + 1;
        __nv_bfloat16 h0 = __float2bfloat16(lo);
        __nv_bfloat16 h1 = __float2bfloat16(hi);
        g_MTH[((size_t)b * D_ + e0) * D_ + row] = h0;
        g_MTL[((size_t)b * D_ + e0) * D_ + row] = __float2bfloat16(lo - __bfloat162float(h0));
        g_MTH[((size_t)b * D_ + e1) * D_ + row] = h1;
        g_MTL[((size_t)b * D_ + e1) * D_ + row] = __float2bfloat16(hi - __bfloat162float(h1));
    }
}

// ---------------- k6: out = query @ M + t, 2 n-tiles per CTA -----------------
__global__ void __launch_bounds__(512, 1)
k6_mma(const float* __restrict__ query, float* __restrict__ out) {
#if TCOK
    extern __shared__ char smem[];
    const u32 sb = smem_u32(smem);
    const int tid = threadIdx.x, wid = tid >> 5, lid = tid & 31;
    const int b = blockIdx.y, n0 = blockIdx.x * 256;

    if (wid == 0) { tmem_alloc(sb + SM_TPTR, 512); tmem_relinquish(); }
    if (tid == 0) { mbar_init(sb + MB0, 1); mbar_init(sb + MB1, 1); }
    __syncthreads();
    u32 tbase;
    asm volatile("ld.shared.b32 %0, [%1];" : "=r"(tbase) : "r"(sb + SM_TPTR));

    const float* qb = query + ((size_t)b * N_ + n0) * D_;
    const size_t bbase0 = (size_t)b * D_ * D_;

    int tA[2], swA[2];
    const float* qsrc[2];
#pragma unroll
    for (int k = 0; k < 2; k++) {
        int i = tid + 512 * k;
        int t = i >> 9, idx = i & 511;
        int rA = idx >> 2, gA = idx & 3;
        tA[k] = t;
        swA[k] = (int)sw64((u32)(rA * 64 + gA * 16));
        qsrc[k] = qb + ((size_t)(t * 128 + rA)) * D_ + gA * 8;
    }

    for (int c = 0; c < 8; c++) {
        const int s = c & 1;
        const int dc = c * 32;
        const u32 ops = sb + SM_OPS + s * OPSET;

        float4 pa[2], pb[2];
#pragma unroll
        for (int k = 0; k < 2; k++) {
            pa[k] = *(const float4*)(qsrc[k] + dc);
            pb[k] = *(const float4*)(qsrc[k] + dc + 4);
        }
        if (c >= 2) mbar_wait(sb + (s ? MB1 : MB0), ((c >> 1) - 1) & 1);

#pragma unroll
        for (int k = 0; k < 2; k++) {
            int i = tid + 512 * k;
            int r = i >> 2, g = i & 3;
            size_t off = bbase0 + (size_t)r * D_ + dc + g * 8;
            u32 sw = sw64((u32)(r * 64 + g * 16));
            cp16(ops + 32768 + sw, g_MTH + off);
            cp16(ops + 49152 + sw, g_MTL + off);
        }
        cp_commit();
#pragma unroll
        for (int k = 0; k < 2; k++) {
            uint4 hv, lv;
            cvt2(pa[k].x, pa[k].y, hv.x, lv.x);
            cvt2(pa[k].z, pa[k].w, hv.y, lv.y);
            cvt2(pb[k].x, pb[k].y, hv.z, lv.z);
            cvt2(pb[k].z, pb[k].w, hv.w, lv.w);
            *(uint4*)(smem + SM_OPS + s * OPSET + tA[k] * 16384 + swA[k]) = hv;
            *(uint4*)(smem + SM_OPS + s * OPSET + tA[k] * 16384 + 8192 + swA[k]) = lv;
        }
        cp_wait<0>();
        __syncthreads();
        fence_async_proxy();
        if (wid == 0 && elect1()) {
            const ull dBH = mk_desc64(ops + 32768), dBL = mk_desc64(ops + 49152);
#pragma unroll
            for (int t = 0; t < 2; t++) {
                const ull aH = mk_desc64(ops + t * 16384);
                const ull aL = mk_desc64(ops + t * 16384 + 8192);
                const u32 dt = tbase + t * 256;
#pragma unroll
                for (int ks = 0; ks < 2; ks++) {
                    ull o = (ull)(ks * 2);
                    mma_f16_ss(dt, aH + o, dBH + o, MMA_IDESC, !(c == 0 && ks == 0));
                    mma_f16_ss(dt, aH + o, dBL + o, MMA_IDESC, 1);
                    mma_f16_ss(dt, aL + o, dBH + o, MMA_IDESC, 1);
                }
            }
            mma_commit(sb + (s ? MB1 : MB0));
        }
    }
    mbar_wait(sb + MB0, 1);
    mbar_wait(sb + MB1, 1);
    tc_fence_after();

    float* stage = (float*)(smem + SM_OPS);   // [2][128][68]
    for (int cb = 0; cb < 4; cb++) {
        __syncthreads();
        if (wid < 8) {
            const int t = wid >> 2, w4 = wid & 3;
            u32 r0a[32], r1a[32];
            LDTM32(r0a, tbase + t * 256 + cb * 64);
            LDTM32(r1a, tbase + t * 256 + cb * 64 + 32);
            tmem_wait_ld();
            float* srow = stage + (size_t)t * 128 * 68 + (w4 * 32 + lid) * 68;
#pragma unroll
            for (int cc = 0; cc < 32; cc++) {
                srow[cc] = __uint_as_float(r0a[cc]);
                srow[32 + cc] = __uint_as_float(r1a[cc]);
            }
        }
        __syncthreads();
#pragma unroll
        for (int k = 0; k < 8; k++) {
            int i = tid + 512 * k;
            int t = i >> 11, j = i & 2047;
            int r = j >> 4, c4 = j & 15;
            float4 v = *(float4*)(stage + (size_t)t * 128 * 68 + r * 68 + c4 * 4);
            int e = cb * 64 + c4 * 4;
            v.x += g_t[b * D_ + e];
            v.y += g_t[b * D_ + e + 1];
            v.z += g_t[b * D_ + e + 2];
            v.w += g_t[b * D_ + e + 3];
            *(float4*)(out + ((size_t)b * N_ + n0 + t * 128 + r) * D_ + e) = v;
        }
    }
    __syncthreads();
    if (tid == 0) { mbar_inval(sb + MB0); mbar_inval(sb + MB1); }
    __syncthreads();
    if (wid == 0) tmem_dealloc(tbase, 512);
#else
    // FFMA fallback
    const int tid = threadIdx.x;
    const int b = blockIdx.y, n0 = blockIdx.x * 256;
    for (int idx = tid; idx < 256 * 256; idx += 512) {
        int n = n0 + (idx >> 8), e = idx & 255;
        const float* q = query + ((size_t)b * N_ + n) * D_;
        const __nv_bfloat16* mh = g_MTH + ((size_t)b * D_ + e) * D_;
        const __nv_bfloat16* ml = g_MTL + ((size_t)b * D_ + e) * D_;
        float acc = g_t[b * D_ + e];
        for (int d = 0; d < D_; d++)
            acc += q[d] * (__bfloat162float(mh[d]) + __bfloat162float(ml[d]));
        out[((size_t)b * N_ + n) * D_ + e] = acc;
    }
#endif
}

// ---------------- launch ----------------
extern "C" void kernel_launch(void* const* d_in, const int* in_sizes, int n_in,
                              void* d_out, int out_size) {
    const float* query = (const float*)d_in[0];
    const float* key   = (const float*)d_in[1];
    const float* value = (const float*)d_in[2];
    const void*  maskraw = d_in[3];
    int o = (n_in >= 11) ? 5 : 4;
    const float* Wq = (const float*)d_in[o + 0];
    const float* bq = (const float*)d_in[o + 1];
    const float* Wk = (const float*)d_in[o + 2];
    const float* bk = (const float*)d_in[o + 3];
    const float* Wv = (const float*)d_in[o + 4];
    const float* bv = (const float*)d_in[o + 5];
    float* out = (float*)d_out;
    (void)in_sizes; (void)out_size;

    cudaFuncSetAttribute(k1_mma, cudaFuncAttributeMaxDynamicSharedMemorySize, K1_TOTAL);
    cudaFuncSetAttribute(k6_mma, cudaFuncAttributeMaxDynamicSharedMemorySize, K6_TOTAL);

    k_zero<<<(B_ * D_ * D_ + 255) / 256, 256>>>();
    k_detect<<<64, 256>>>((const unsigned char*)maskraw);
    k_maskconv<<<(B_ * N_) / 256, 256>>>(maskraw);
    k1_mma<<<dim3(16, B_), 512, K1_TOTAL>>>(key, value);
    k_uw<<<B_, 256>>>(Wk, Wv);
    k23_TA<<<dim3(16, B_), 256>>>(Wk, Wv, bk, bv);
    k4_softmax<<<dim3(32, B_), 256>>>(bq);
    k5_M<<<dim3(16, B_), 256>>>(Wq);
    k6_mma<<<dim3(32, B_), 512, K6_TOTAL>>>(query, out);
}

// round 15
// speedup vs baseline: 1.1866x; 1.1400x over previous
#include <cuda_runtime.h>
#include <cuda_bf16.h>
#include <cstdint>
#include <cstddef>

#define B_ 8
#define N_ 8192
#define D_ 256
#define NCHUNK 16

typedef unsigned long long ull;
typedef unsigned int u32;

#if !defined(__CUDA_ARCH__) || defined(__CUDA_ARCH_FEAT_SM103_ALL) || defined(__CUDA_ARCH_FEAT_SM100_ALL) || defined(__CUDA_ARCH_FEAT_SM101_ALL)
#define TCOK 1
#else
#define TCOK 0
#endif

// ---------------- device scratch ----------------
__device__ float g_Sp[NCHUNK * B_ * D_ * D_];   // per-chunk partial S (32 MB)
__device__ __nv_bfloat16 g_MTH[B_ * D_ * D_];   // (Wq^T aw)^T hi [b][e][i]
__device__ __nv_bfloat16 g_MTL[B_ * D_ * D_];
__device__ float g_S[B_ * D_ * D_];
__device__ float g_A[B_ * D_ * D_];
__device__ float g_rk[B_ * D_];
__device__ float g_rv[B_ * D_];
__device__ float g_u[B_ * D_];
__device__ float g_w[B_ * D_];
__device__ float g_t[B_ * D_];
__device__ float g_cm[B_];
__device__ int   g_kind;
__device__ float g_m[B_ * N_];

// ---------------- scalar helpers ----------------
__device__ __forceinline__ ull pack2(float lo, float hi) {
    ull r; asm("mov.b64 %0, {%1,%2};" : "=l"(r) : "f"(lo), "f"(hi)); return r;
}
__device__ __forceinline__ void unpack2(ull v, float& lo, float& hi) {
    asm("mov.b64 {%0,%1}, %2;" : "=f"(lo), "=f"(hi) : "l"(v));
}
__device__ __forceinline__ ull ffma2(ull a, ull b, ull c) {
    ull d; asm("fma.rn.f32x2 %0, %1, %2, %3;" : "=l"(d) : "l"(a), "l"(b), "l"(c)); return d;
}
__device__ __forceinline__ u32 prmt7632(u32 a, u32 b) {
    u32 d; asm("prmt.b32 %0, %1, %2, 0x7632;" : "=r"(d) : "r"(a), "r"(b)); return d;
}
// f32 pair -> bf16x2 hi (truncated) + bf16x2 lo (residual, truncated). err ~2^-16.
__device__ __forceinline__ void cvt2(float x0, float x1, u32& h2, u32& l2) {
    u32 u0 = __float_as_uint(x0), u1 = __float_as_uint(x1);
    h2 = prmt7632(u0, u1);
    float l0 = x0 - __uint_as_float(u0 & 0xFFFF0000u);
    float l1 = x1 - __uint_as_float(u1 & 0xFFFF0000u);
    l2 = prmt7632(__float_as_uint(l0), __float_as_uint(l1));
}

// ---------------- tcgen05 / async helpers (guarded) ----------------
#if TCOK
__device__ __forceinline__ u32 smem_u32(const void* p) {
    u32 a; asm("{ .reg .u64 t; cvta.to.shared.u64 t, %1; cvt.u32.u64 %0, t; }" : "=r"(a) : "l"(p));
    return a;
}
__device__ __forceinline__ int elect1() {
    u32 p;
    asm volatile("{\n\t.reg .pred p;\n\telect.sync _|p, 0xFFFFFFFF;\n\tselp.b32 %0, 1, 0, p;\n\t}" : "=r"(p));
    return (int)p;
}
__device__ __forceinline__ void cp16(u32 dst, const void* src) {
    asm volatile("cp.async.cg.shared.global [%0], [%1], 16;" :: "r"(dst), "l"(src) : "memory");
}
__device__ __forceinline__ void cp_commit() {
    asm volatile("cp.async.commit_group;" ::: "memory");
}
template <int N>
__device__ __forceinline__ void cp_wait() {
    asm volatile("cp.async.wait_group %0;" :: "n"(N) : "memory");
}
__device__ __forceinline__ void mbar_init(u32 mbar, u32 cnt) {
    asm volatile("mbarrier.init.shared.b64 [%0], %1;" :: "r"(mbar), "r"(cnt) : "memory");
}
__device__ __forceinline__ void mbar_inval(u32 mbar) {
    asm volatile("mbarrier.inval.shared.b64 [%0];" :: "r"(mbar) : "memory");
}
__device__ __forceinline__ void mbar_wait(u32 mbar, u32 parity) {
    asm volatile(
        "{\n\t.reg .pred P;\n\t"
        "WL_%=:\n\t"
        "mbarrier.try_wait.parity.acquire.cta.shared::cta.b64 P, [%0], %1, 0x989680;\n\t"
        "@P bra WD_%=;\n\t"
        "bra.uni WL_%=;\n\t"
        "WD_%=:\n\t}"
        :: "r"(mbar), "r"(parity) : "memory");
}
__device__ __forceinline__ void tmem_alloc(u32 smem_dst, u32 ncols) {
    asm volatile("tcgen05.alloc.cta_group::1.sync.aligned.shared::cta.b32 [%0], %1;"
                 :: "r"(smem_dst), "r"(ncols) : "memory");
}
__device__ __forceinline__ void tmem_relinquish() {
    asm volatile("tcgen05.relinquish_alloc_permit.cta_group::1.sync.aligned;");
}
__device__ __forceinline__ void tmem_dealloc(u32 tmem, u32 ncols) {
    asm volatile("tcgen05.dealloc.cta_group::1.sync.aligned.b32 %0, %1;" :: "r"(tmem), "r"(ncols));
}
__device__ __forceinline__ void mma_f16_ss(u32 d_tmem, ull a_desc, ull b_desc, u32 idesc, int accum) {
    u32 z = 0;
    asm volatile(
        "{\n\t.reg .pred p;\n\tsetp.ne.u32 p, %5, 0;\n\t"
        "tcgen05.mma.cta_group::1.kind::f16 [%0], %1, %2, %3, {%4, %4, %4, %4}, p;\n\t}"
        :: "r"(d_tmem), "l"(a_desc), "l"(b_desc), "r"(idesc), "r"(z), "r"((u32)accum) : "memory");
}
__device__ __forceinline__ void mma_commit(u32 mbar) {
    asm volatile("tcgen05.commit.cta_group::1.mbarrier::arrive::one.shared::cluster.b64 [%0];"
                 :: "r"(mbar) : "memory");
}
__device__ __forceinline__ void fence_async_proxy() {
    asm volatile("fence.proxy.async.shared::cta;" ::: "memory");
}
__device__ __forceinline__ void tc_fence_after() {
    asm volatile("tcgen05.fence::after_thread_sync;" ::: "memory");
}
__device__ __forceinline__ void tmem_wait_ld() {
    asm volatile("tcgen05.wait::ld.sync.aligned;" ::: "memory");
}

#define LDTM32(r, addr)                                                      \
    asm volatile("tcgen05.ld.sync.aligned.32x32b.x32.b32 "                   \
        "{%0, %1, %2, %3, %4, %5, %6, %7, %8, %9, %10, %11, %12, %13, %14, %15, " \
        " %16, %17, %18, %19, %20, %21, %22, %23, %24, %25, %26, %27, %28, %29, %30, %31}, [%32];" \
        : "=r"((r)[0]), "=r"((r)[1]), "=r"((r)[2]), "=r"((r)[3]),            \
          "=r"((r)[4]), "=r"((r)[5]), "=r"((r)[6]), "=r"((r)[7]),            \
          "=r"((r)[8]), "=r"((r)[9]), "=r"((r)[10]), "=r"((r)[11]),          \
          "=r"((r)[12]), "=r"((r)[13]), "=r"((r)[14]), "=r"((r)[15]),        \
          "=r"((r)[16]), "=r"((r)[17]), "=r"((r)[18]), "=r"((r)[19]),        \
          "=r"((r)[20]), "=r"((r)[21]), "=r"((r)[22]), "=r"((r)[23]),        \
          "=r"((r)[24]), "=r"((r)[25]), "=r"((r)[26]), "=r"((r)[27]),        \
          "=r"((r)[28]), "=r"((r)[29]), "=r"((r)[30]), "=r"((r)[31])         \
        : "r"(addr))

__device__ __forceinline__ u32 sw64(u32 off)  { return off ^ ((off >> 3) & 0x30); }

#define DESC_BASE64 ((4ull << 61) | (1ull << 46) | (32ull << 32) | (1ull << 16))
__device__ __forceinline__ ull mk_desc64(u32 addr) { return DESC_BASE64 | ((ull)(addr >> 4) & 0x3FFF); }

#define MMA_IDESC 0x8400490u   // F32 accum, BF16xBF16, M=128, N=256
#endif  // TCOK

// ---- k1 layout: hdr | masks (2KB) | 2x opset ----
#define SM_TPTR 0
#define MB0 8
#define MB1 16
#define SM_MASKS 128                    // 512 floats
#define K1_OPS 4096
#define OPSET 65536                     // A0H 8K|A0L 8K|A1H 8K|A1L 8K|BH 16K|BL 16K
#define K1_TOTAL (K1_OPS + 2 * OPSET)   // 135168

// ---- k6 layout ----
#define SM_OPS 1024
#define K6_TOTAL (1024 + 2 * OPSET)     // 132096

// ---------------- mask detect + canonicalize (+cm) ----------------
__global__ void k_detect(const unsigned char* __restrict__ raw) {
    int idx = blockIdx.x * blockDim.x + threadIdx.x;   // < 16384
    if (raw[idx * 4 + 1] != 0) atomicOr(&g_kind, 1);
}

__global__ void k_maskconv(const void* __restrict__ rawv) {
    int n = blockIdx.x * blockDim.x + threadIdx.x;
    bool padded;
    if (g_kind) padded = ((const unsigned char*)rawv)[n] != 0;
    else        padded = ((const unsigned int*)rawv)[n] != 0u;
    float m = padded ? 0.f : 1.f;
    g_m[n] = m;
    float s = m;
#pragma unroll
    for (int o = 16; o > 0; o >>= 1) s += __shfl_xor_sync(0xffffffffu, s, o);
    __shared__ float red[8];
    int wid = threadIdx.x >> 5, lane = threadIdx.x & 31;
    if (lane == 0) red[wid] = s;
    __syncthreads();
    if (threadIdx.x == 0) {
        float t = 0.f;
        for (int i = 0; i < 8; i++) t += red[i];
        atomicAdd(&g_cm[n >> 13], t);
    }
}

__global__ void k_zero() {
    int i = blockIdx.x * blockDim.x + threadIdx.x;
    if (i < B_ * D_) { g_rk[i] = 0.f; g_rv[i] = 0.f; }
    if (i < B_) g_cm[i] = 0.f;
    if (i == 0) g_kind = 0;
}

// ---------------- k1: partial S via tcgen05, STG epilogue (no atomics) -------
// grid (16 chunks, B), 512 threads, single wave. 16 windows of n=32, K=32 SW64.
__global__ void __launch_bounds__(512, 1)
k1_mma(const float* __restrict__ key, const float* __restrict__ value) {
#if TCOK
    extern __shared__ char smem[];
    const u32 sb = smem_u32(smem);
    const int tid = threadIdx.x, wid = tid >> 5, lid = tid & 31;
    const int b = blockIdx.y, chunk = blockIdx.x;
    const int n_start = chunk * 512;

    if (wid == 0) { tmem_alloc(sb + SM_TPTR, 512); tmem_relinquish(); }
    if (tid == 0) { mbar_init(sb + MB0, 1); mbar_init(sb + MB1, 1); }
    float* smask = (float*)(smem + SM_MASKS);
    smask[tid] = g_m[(size_t)b * N_ + n_start + tid];     // whole-chunk masks
    __syncthreads();
    u32 tbase;
    asm volatile("ld.shared.b32 %0, [%1];" : "=r"(tbase) : "r"(sb + SM_TPTR));

    // per-thread fixed slot geometry (A and B share the mapping)
    int rS[2], gS[2];
    const float* kb_[2];
    const float* vb_[2];
    u32 swS[2], tbS[2];
#pragma unroll
    for (int k = 0; k < 2; k++) {
        int i = tid + 512 * k;
        rS[k] = i & 255; gS[k] = i >> 8;                  // g 0..3
        kb_[k] = key + ((size_t)b * N_ + n_start + gS[k] * 8) * D_ + rS[k];
        vb_[k] = value + ((size_t)b * N_ + n_start + gS[k] * 8) * D_ + rS[k];
        swS[k] = sw64((u32)((rS[k] & 127) * 64 + gS[k] * 16));
        tbS[k] = (u32)(rS[k] >> 7) * 16384;
    }

    float fA[2][8], fB[2][8];
#pragma unroll
    for (int k = 0; k < 2; k++)
#pragma unroll
        for (int j = 0; j < 8; j++) {
            fA[k][j] = kb_[k][(size_t)j * D_];
            fB[k][j] = vb_[k][(size_t)j * D_];
        }

    float skacc = 0.f, svacc = 0.f;

    for (int c = 0; c < 16; c++) {
        const int s = c & 1;
        const u32 ops = sb + K1_OPS + s * OPSET;
        if (c >= 2) mbar_wait(sb + (s ? MB1 : MB0), ((c >> 1) - 1) & 1);

        // ---- A: masked key -> two M=128 tiles; then reload regs for c+1 ----
#pragma unroll
        for (int k = 0; k < 2; k++) {
            const float* msk = smask + c * 32 + gS[k] * 8;
            float t[8];
#pragma unroll
            for (int j = 0; j < 8; j++) { t[j] = fA[k][j] * msk[j]; skacc += t[j]; }
            uint4 hv, lv;
            cvt2(t[0], t[1], hv.x, lv.x);
            cvt2(t[2], t[3], hv.y, lv.y);
            cvt2(t[4], t[5], hv.z, lv.z);
            cvt2(t[6], t[7], hv.w, lv.w);
            *(uint4*)(smem + K1_OPS + s * OPSET + tbS[k] + swS[k]) = hv;
            *(uint4*)(smem + K1_OPS + s * OPSET + tbS[k] + 8192 + swS[k]) = lv;
            if (c < 15) {
                const float* src = kb_[k] + (size_t)(c + 1) * 32 * D_;
#pragma unroll
                for (int j = 0; j < 8; j++) fA[k][j] = src[(size_t)j * D_];
            }
        }
        // ---- B: raw value; masked side sums; reload regs for c+1 ----
#pragma unroll
        for (int k = 0; k < 2; k++) {
            const float* msk = smask + c * 32 + gS[k] * 8;
#pragma unroll
            for (int j = 0; j < 8; j++) svacc += msk[j] * fB[k][j];
            uint4 hv, lv;
            cvt2(fB[k][0], fB[k][1], hv.x, lv.x);
            cvt2(fB[k][2], fB[k][3], hv.y, lv.y);
            cvt2(fB[k][4], fB[k][5], hv.z, lv.z);
            cvt2(fB[k][6], fB[k][7], hv.w, lv.w);
            u32 sw = sw64((u32)(rS[k] * 64 + gS[k] * 16));
            *(uint4*)(smem + K1_OPS + s * OPSET + 32768 + sw) = hv;
            *(uint4*)(smem + K1_OPS + s * OPSET + 49152 + sw) = lv;
            if (c < 15) {
                const float* src = vb_[k] + (size_t)(c + 1) * 32 * D_;
#pragma unroll
                for (int j = 0; j < 8; j++) fB[k][j] = src[(size_t)j * D_];
            }
        }
        __syncthreads();
        fence_async_proxy();
        if (wid == 0 && elect1()) {
            const ull dBH = mk_desc64(ops + 32768), dBL = mk_desc64(ops + 49152);
#pragma unroll
            for (int t = 0; t < 2; t++) {
                const ull aH = mk_desc64(ops + t * 16384);
                const ull aL = mk_desc64(ops + t * 16384 + 8192);
                const u32 dt = tbase + t * 256;
#pragma unroll
                for (int ks = 0; ks < 2; ks++) {
                    ull o = (ull)(ks * 2);
                    mma_f16_ss(dt, aH + o, dBH + o, MMA_IDESC, !(c == 0 && ks == 0));
                    mma_f16_ss(dt, aH + o, dBL + o, MMA_IDESC, 1);
                    mma_f16_ss(dt, aL + o, dBH + o, MMA_IDESC, 1);
                }
            }
            mma_commit(sb + (s ? MB1 : MB0));
        }
    }
    mbar_wait(sb + MB0, 1);   // 8 commits each -> final parity 1
    mbar_wait(sb + MB1, 1);
    tc_fence_after();

    // ---- epilogue: TMEM -> smem stage -> coalesced STG to partial buffer ----
    float* stage = (float*)(smem + K1_OPS);   // [2][128][68] = 69632 B
    float* dstS = g_Sp + ((size_t)chunk * B_ + b) * D_ * D_;
    for (int cb = 0; cb < 4; cb++) {
        __syncthreads();
        if (wid < 8) {
            const int t = wid >> 2, w4 = wid & 3;
            u32 r0a[32], r1a[32];
            LDTM32(r0a, tbase + t * 256 + cb * 64);
            LDTM32(r1a, tbase + t * 256 + cb * 64 + 32);
            tmem_wait_ld();
            float* srow = stage + (size_t)t * 128 * 68 + (w4 * 32 + lid) * 68;
#pragma unroll
            for (int cc = 0; cc < 32; cc++) {
                srow[cc] = __uint_as_float(r0a[cc]);
                srow[32 + cc] = __uint_as_float(r1a[cc]);
            }
        }
        __syncthreads();
#pragma unroll
        for (int k = 0; k < 8; k++) {
            int i = tid + 512 * k;              // 4096 float4 slots
            int t = i >> 11, j = i & 2047;
            int r = j >> 4, c4 = j & 15;
            float4 v = *(float4*)(stage + (size_t)t * 128 * 68 + r * 68 + c4 * 4);
            *(float4*)(dstS + (size_t)(t * 128 + r) * D_ + cb * 64 + c4 * 4) = v;
        }
    }
    __syncthreads();
    float* sredA = (float*)(smem + K1_OPS);   // stage free now
    float* sredB = sredA + 512;
    sredA[tid] = skacc;
    sredB[tid] = svacc;
    __syncthreads();
    if (tid < 256) {
        atomicAdd(&g_rk[b * D_ + tid], sredA[tid] + sredA[tid + 256]);
        atomicAdd(&g_rv[b * D_ + tid], sredB[tid] + sredB[tid + 256]);
    }
    __syncthreads();
    if (tid == 0) { mbar_inval(sb + MB0); mbar_inval(sb + MB1); }
    __syncthreads();
    if (wid == 0) tmem_dealloc(tbase, 512);
#else
    // FFMA fallback (non-'a' PTX stage only)
    const int tid = threadIdx.x;
    const int b = blockIdx.y, chunk = blockIdx.x;
    const int n_start = chunk * 512;
    float* dstS = g_Sp + ((size_t)chunk * B_ + b) * D_ * D_;
    for (int idx = tid; idx < 256 * 256; idx += 512) {
        int d = idx >> 8, e = idx & 255;
        float acc = 0.f;
        for (int n = n_start; n < n_start + 512; n++) {
            float m = g_m[(size_t)b * N_ + n];
            acc += m * key[((size_t)b * N_ + n) * D_ + d] * value[((size_t)b * N_ + n) * D_ + e];
        }
        dstS[(size_t)d * D_ + e] = acc;
    }
    if (tid < 256) {
        float sk = 0.f, sv = 0.f;
        for (int n = n_start; n < n_start + 512; n++) {
            float m = g_m[(size_t)b * N_ + n];
            sk += m * key[((size_t)b * N_ + n) * D_ + tid];
            sv += m * value[((size_t)b * N_ + n) * D_ + tid];
        }
        atomicAdd(&g_rk[b * D_ + tid], sk);
        atomicAdd(&g_rv[b * D_ + tid], sv);
    }
#endif
}

// ---------------- k1_red: S = sum over chunks of g_Sp ----------------
__global__ void k1_red() {
    size_t i = ((size_t)blockIdx.x * blockDim.x + threadIdx.x) * 4;  // float idx
    float4 acc = make_float4(0.f, 0.f, 0.f, 0.f);
#pragma unroll
    for (int c = 0; c < NCHUNK; c++) {
        float4 v = *(const float4*)(g_Sp + (size_t)c * B_ * D_ * D_ + i);
        acc.x += v.x; acc.y += v.y; acc.z += v.z; acc.w += v.w;
    }
    *(float4*)(g_S + i) = acc;
}

// ---------------- k_uw: u = Wk@rk, w = Wv@rv ----------------
__global__ void k_uw(const float* __restrict__ Wk, const float* __restrict__ Wv) {
    int b = blockIdx.x, d = threadIdx.x;
    float su = 0.f, sw = 0.f;
    for (int i = 0; i < D_; i++) {
        su += Wk[d * D_ + i] * g_rk[b * D_ + i];
        sw += Wv[d * D_ + i] * g_rv[b * D_ + i];
    }
    g_u[b * D_ + d] = su;
    g_w[b * D_ + d] = sw;
}

// ---------------- k23: T1 tile = Wk @ S (smem), then A = (T1 @ Wv^T + r1)/sqrt8
__global__ void __launch_bounds__(256, 1)
k23_TA(const float* __restrict__ Wk, const float* __restrict__ Wv,
       const float* __restrict__ bk, const float* __restrict__ bv) {
    const int b = blockIdx.y, d0 = blockIdx.x * 16;
    const int tid = threadIdx.x, tx = tid & 15, ty = tid >> 4;
    __shared__ float sA[16][16];
    __shared__ float sB[16][256];
    __shared__ float sT1[16][258];
    ull acc[8];
#pragma unroll
    for (int p = 0; p < 8; p++) acc[p] = 0ull;
    const float* Sb = g_S + b * D_ * D_;
    for (int i0 = 0; i0 < D_; i0 += 16) {
        __syncthreads();
        if (tid < 64) {
            int r = tid >> 2, q = tid & 3;
            *(float4*)&sA[r][q * 4] = *(const float4*)(Wk + (size_t)(d0 + r) * D_ + i0 + q * 4);
        }
#pragma unroll
        for (int i = 0; i < 4; i++) {
            int idx = tid + 256 * i;
            int r = idx >> 6, q = idx & 63;
            *(float4*)&sB[r][q * 4] = *(const float4*)(Sb + (size_t)(i0 + r) * D_ + q * 4);
        }
        __syncthreads();
#pragma unroll
        for (int ii = 0; ii < 16; ii++) {
            float a = sA[ty][ii];
            ull a2 = pack2(a, a);
#pragma unroll
            for (int p = 0; p < 8; p++)
                acc[p] = ffma2(a2, *(const ull*)&sB[ii][2 * tx + 32 * p], acc[p]);
        }
    }
#pragma unroll
    for (int p = 0; p < 8; p++) {
        float lo, hi; unpack2(acc[p], lo, hi);
        sT1[ty][2 * tx + 32 * p] = lo;
        sT1[ty][2 * tx + 32 * p + 1] = hi;
    }
    __syncthreads();
#pragma unroll
    for (int p = 0; p < 8; p++) acc[p] = 0ull;
    for (int j0 = 0; j0 < D_; j0 += 16) {
        __syncthreads();
#pragma unroll
        for (int i = 0; i < 4; i++) {
            int idx = tid + 256 * i;
            int q = idx & 3, e = idx >> 2;
            float4 v = *(const float4*)(Wv + (size_t)e * D_ + j0 + q * 4);
            sB[q * 4 + 0][e] = v.x; sB[q * 4 + 1][e] = v.y;
            sB[q * 4 + 2][e] = v.z; sB[q * 4 + 3][e] = v.w;
        }
        __syncthreads();
#pragma unroll
        for (int jj = 0; jj < 16; jj++) {
            float a = sT1[ty][j0 + jj];
            ull a2 = pack2(a, a);
#pragma unroll
            for (int p = 0; p < 8; p++)
                acc[p] = ffma2(a2, *(const ull*)&sB[jj][2 * tx + 32 * p], acc[p]);
        }
    }
    const int d = d0 + ty;
    const float u_d = g_u[b * D_ + d], bk_d = bk[d], cmv = g_cm[b];
    const float inv = 0.3535533905932738f;
    float* Ab = g_A + b * D_ * D_;
#pragma unroll
    for (int p = 0; p < 8; p++) {
        float lo, hi; unpack2(acc[p], lo, hi);
        int e = 2 * tx + 32 * p;
        float bv0 = bv[e], bv1 = bv[e + 1];
        float w0 = g_w[b * D_ + e], w1 = g_w[b * D_ + e + 1];
        lo = (lo + u_d * bv0 + bk_d * w0 + cmv * bk_d * bv0) * inv;
        hi = (hi + u_d * bv1 + bk_d * w1 + cmv * bk_d * bv1) * inv;
        *(float2*)&Ab[d * D_ + e] = make_float2(lo, hi);
    }
}

// ---------------- k4: column softmax + t = bq^T aw ----------------
__global__ void k4_softmax(const float* __restrict__ bq) {
    const int b = blockIdx.y;
    const int w = threadIdx.x >> 5, lane = threadIdx.x & 31;
    const int e = blockIdx.x * 8 + w;
    float* col = g_A + b * D_ * D_ + e;
    float v[8];
#pragma unroll
    for (int s = 0; s < 8; s++) v[s] = col[(lane + 32 * s) * D_];
    float mx = v[0];
#pragma unroll
    for (int s = 1; s < 8; s++) mx = fmaxf(mx, v[s]);
#pragma unroll
    for (int o = 16; o > 0; o >>= 1) mx = fmaxf(mx, __shfl_xor_sync(0xffffffffu, mx, o));
    float sum = 0.f;
#pragma unroll
    for (int s = 0; s < 8; s++) { v[s] = expf(v[s] - mx); sum += v[s]; }
#pragma unroll
    for (int o = 16; o > 0; o >>= 1) sum += __shfl_xor_sync(0xffffffffu, sum, o);
    const float isum = 1.f / sum;
    float tacc = 0.f;
#pragma unroll
    for (int s = 0; s < 8; s++) {
        float p = v[s] * isum;
        col[(lane + 32 * s) * D_] = p;
        tacc += p * bq[lane + 32 * s];
    }
#pragma unroll
    for (int o = 16; o > 0; o >>= 1) tacc += __shfl_xor_sync(0xffffffffu, tacc, o);
    if (lane == 0) g_t[b * D_ + e] = tacc;
}

// ---------------- k5: M^T[e][i] = sum_d Wq[d][i] aw[d][e] -> bf16 hi/lo ------
__global__ void __launch_bounds__(256, 1)
k5_M(const float* __restrict__ Wq) {
    const int b = blockIdx.y, i0 = blockIdx.x * 16;
    const int tid = threadIdx.x, tx = tid & 15, ty = tid >> 4;
    __shared__ float sA[16][17];
    __shared__ float sB[16][256];
    ull acc[8];
#pragma unroll
    for (int p = 0; p < 8; p++) acc[p] = 0ull;
    const float* awb = g_A + b * D_ * D_;
    for (int dd0 = 0; dd0 < D_; dd0 += 16) {
        __syncthreads();
        if (tid < 64) {
            int r = tid >> 2, q = tid & 3;
            float4 v = *(const float4*)(Wq + (size_t)(dd0 + r) * D_ + i0 + q * 4);
            sA[q * 4 + 0][r] = v.x; sA[q * 4 + 1][r] = v.y;
            sA[q * 4 + 2][r] = v.z; sA[q * 4 + 3][r] = v.w;
        }
#pragma unroll
        for (int i = 0; i < 4; i++) {
            int idx = tid + 256 * i;
            int r = idx >> 6, q = idx & 63;
            *(float4*)&sB[r][q * 4] = *(const float4*)(awb + (size_t)(dd0 + r) * D_ + q * 4);
        }
        __syncthreads();
#pragma unroll
        for (int dd = 0; dd < 16; dd++) {
            float a = sA[ty][dd];
            ull a2 = pack2(a, a);
#pragma unroll
            for (int p = 0; p < 8; p++)
                acc[p] = ffma2(a2, *(const ull*)&sB[dd][2 * tx + 32 * p], acc[p]);
        }
    }
    const int row = i0 + ty;
#pragma unroll
    for (int p = 0; p < 8; p++) {
        float lo, hi; unpack2(acc[p], lo, hi);
        int e0 = 2 * tx + 32 * p, e1 = e0 + 1;
        __nv_bfloat16 h0 = __float2bfloat16(lo);
        __nv_bfloat16 h1 = __float2bfloat16(hi);
        g_MTH[((size_t)b * D_ + e0) * D_ + row] = h0;
        g_MTL[((size_t)b * D_ + e0) * D_ + row] = __float2bfloat16(lo - __bfloat162float(h0));
        g_MTH[((size_t)b * D_ + e1) * D_ + row] = h1;
        g_MTL[((size_t)b * D_ + e1) * D_ + row] = __float2bfloat16(hi - __bfloat162float(h1));
    }
}

// ---------------- k6: out = query @ M + t, 2 n-tiles per CTA -----------------
__global__ void __launch_bounds__(512, 1)
k6_mma(const float* __restrict__ query, float* __restrict__ out) {
#if TCOK
    extern __shared__ char smem[];
    const u32 sb = smem_u32(smem);
    const int tid = threadIdx.x, wid = tid >> 5, lid = tid & 31;
    const int b = blockIdx.y, n0 = blockIdx.x * 256;

    if (wid == 0) { tmem_alloc(sb + SM_TPTR, 512); tmem_relinquish(); }
    if (tid == 0) { mbar_init(sb + MB0, 1); mbar_init(sb + MB1, 1); }
    __syncthreads();
    u32 tbase;
    asm volatile("ld.shared.b32 %0, [%1];" : "=r"(tbase) : "r"(sb + SM_TPTR));

    const float* qb = query + ((size_t)b * N_ + n0) * D_;
    const size_t bbase0 = (size_t)b * D_ * D_;

    int tA[2], swA[2];
    const float* qsrc[2];
#pragma unroll
    for (int k = 0; k < 2; k++) {
        int i = tid + 512 * k;
        int t = i >> 9, idx = i & 511;
        int rA = idx >> 2, gA = idx & 3;
        tA[k] = t;
        swA[k] = (int)sw64((u32)(rA * 64 + gA * 16));
        qsrc[k] = qb + ((size_t)(t * 128 + rA)) * D_ + gA * 8;
    }

    for (int c = 0; c < 8; c++) {
        const int s = c & 1;
        const int dc = c * 32;
        const u32 ops = sb + SM_OPS + s * OPSET;

        float4 pa[2], pb[2];
#pragma unroll
        for (int k = 0; k < 2; k++) {
            pa[k] = *(const float4*)(qsrc[k] + dc);
            pb[k] = *(const float4*)(qsrc[k] + dc + 4);
        }
        if (c >= 2) mbar_wait(sb + (s ? MB1 : MB0), ((c >> 1) - 1) & 1);

#pragma unroll
        for (int k = 0; k < 2; k++) {
            int i = tid + 512 * k;
            int r = i >> 2, g = i & 3;
            size_t off = bbase0 + (size_t)r * D_ + dc + g * 8;
            u32 sw = sw64((u32)(r * 64 + g * 16));
            cp16(ops + 32768 + sw, g_MTH + off);
            cp16(ops + 49152 + sw, g_MTL + off);
        }
        cp_commit();
#pragma unroll
        for (int k = 0; k < 2; k++) {
            uint4 hv, lv;
            cvt2(pa[k].x, pa[k].y, hv.x, lv.x);
            cvt2(pa[k].z, pa[k].w, hv.y, lv.y);
            cvt2(pb[k].x, pb[k].y, hv.z, lv.z);
            cvt2(pb[k].z, pb[k].w, hv.w, lv.w);
            *(uint4*)(smem + SM_OPS + s * OPSET + tA[k] * 16384 + swA[k]) = hv;
            *(uint4*)(smem + SM_OPS + s * OPSET + tA[k] * 16384 + 8192 + swA[k]) = lv;
        }
        cp_wait<0>();
        __syncthreads();
        fence_async_proxy();
        if (wid == 0 && elect1()) {
            const ull dBH = mk_desc64(ops + 32768), dBL = mk_desc64(ops + 49152);
#pragma unroll
            for (int t = 0; t < 2; t++) {
                const ull aH = mk_desc64(ops + t * 16384);
                const ull aL = mk_desc64(ops + t * 16384 + 8192);
                const u32 dt = tbase + t * 256;
#pragma unroll
                for (int ks = 0; ks < 2; ks++) {
                    ull o = (ull)(ks * 2);
                    mma_f16_ss(dt, aH + o, dBH + o, MMA_IDESC, !(c == 0 && ks == 0));
                    mma_f16_ss(dt, aH + o, dBL + o, MMA_IDESC, 1);
                    mma_f16_ss(dt, aL + o, dBH + o, MMA_IDESC, 1);
                }
            }
            mma_commit(sb + (s ? MB1 : MB0));
        }
    }
    mbar_wait(sb + MB0, 1);
    mbar_wait(sb + MB1, 1);
    tc_fence_after();

    float* stage = (float*)(smem + SM_OPS);   // [2][128][68]
    for (int cb = 0; cb < 4; cb++) {
        __syncthreads();
        if (wid < 8) {
            const int t = wid >> 2, w4 = wid & 3;
            u32 r0a[32], r1a[32];
            LDTM32(r0a, tbase + t * 256 + cb * 64);
            LDTM32(r1a, tbase + t * 256 + cb * 64 + 32);
            tmem_wait_ld();
            float* srow = stage + (size_t)t * 128 * 68 + (w4 * 32 + lid) * 68;
#pragma unroll
            for (int cc = 0; cc < 32; cc++) {
                srow[cc] = __uint_as_float(r0a[cc]);
                srow[32 + cc] = __uint_as_float(r1a[cc]);
            }
        }
        __syncthreads();
#pragma unroll
        for (int k = 0; k < 8; k++) {
            int i = tid + 512 * k;
            int t = i >> 11, j = i & 2047;
            int r = j >> 4, c4 = j & 15;
            float4 v = *(float4*)(stage + (size_t)t * 128 * 68 + r * 68 + c4 * 4);
            int e = cb * 64 + c4 * 4;
            v.x += g_t[b * D_ + e];
            v.y += g_t[b * D_ + e + 1];
            v.z += g_t[b * D_ + e + 2];
            v.w += g_t[b * D_ + e + 3];
            *(float4*)(out + ((size_t)b * N_ + n0 + t * 128 + r) * D_ + e) = v;
        }
    }
    __syncthreads();
    if (tid == 0) { mbar_inval(sb + MB0); mbar_inval(sb + MB1); }
    __syncthreads();
    if (wid == 0) tmem_dealloc(tbase, 512);
#else
    // FFMA fallback
    const int tid = threadIdx.x;
    const int b = blockIdx.y, n0 = blockIdx.x * 256;
    for (int idx = tid; idx < 256 * 256; idx += 512) {
        int n = n0 + (idx >> 8), e = idx & 255;
        const float* q = query + ((size_t)b * N_ + n) * D_;
        const __nv_bfloat16* mh = g_MTH + ((size_t)b * D_ + e) * D_;
        const __nv_bfloat16* ml = g_MTL + ((size_t)b * D_ + e) * D_;
        float acc = g_t[b * D_ + e];
        for (int d = 0; d < D_; d++)
            acc += q[d] * (__bfloat162float(mh[d]) + __bfloat162float(ml[d]));
        out[((size_t)b * N_ + n) * D_ + e] = acc;
    }
#endif
}

// ---------------- launch ----------------
extern "C" void kernel_launch(void* const* d_in, const int* in_sizes, int n_in,
                              void* d_out, int out_size) {
    const float* query = (const float*)d_in[0];
    const float* key   = (const float*)d_in[1];
    const float* value = (const float*)d_in[2];
    const void*  maskraw = d_in[3];
    int o = (n_in >= 11) ? 5 : 4;
    const float* Wq = (const float*)d_in[o + 0];
    const float* bq = (const float*)d_in[o + 1];
    const float* Wk = (const float*)d_in[o + 2];
    const float* bk = (const float*)d_in[o + 3];
    const float* Wv = (const float*)d_in[o + 4];
    const float* bv = (const float*)d_in[o + 5];
    float* out = (float*)d_out;
    (void)in_sizes; (void)out_size;

    cudaFuncSetAttribute(k1_mma, cudaFuncAttributeMaxDynamicSharedMemorySize, K1_TOTAL);
    cudaFuncSetAttribute(k6_mma, cudaFuncAttributeMaxDynamicSharedMemorySize, K6_TOTAL);

    k_zero<<<8, 256>>>();
    k_detect<<<64, 256>>>((const unsigned char*)maskraw);
    k_maskconv<<<(B_ * N_) / 256, 256>>>(maskraw);
    k1_mma<<<dim3(NCHUNK, B_), 512, K1_TOTAL>>>(key, value);
    k1_red<<<(B_ * D_ * D_ / 4) / 256, 256>>>();
    k_uw<<<B_, 256>>>(Wk, Wv);
    k23_TA<<<dim3(16, B_), 256>>>(Wk, Wv, bk, bv);
    k4_softmax<<<dim3(32, B_), 256>>>(bq);
    k5_M<<<dim3(16, B_), 256>>>(Wq);
    k6_mma<<<dim3(32, B_), 512, K6_TOTAL>>>(query, out);
}